// round 1
// baseline (speedup 1.0000x reference)
#include <cuda_runtime.h>
#include <math.h>

#define BATCH 4096
#define OBJ   16
#define OBS   256
#define HID   512

// Scratch (no allocation allowed in kernel_launch)
__device__ float g_sbar[BATCH * OBS];   // mean over objects of states
__device__ float g_h1[BATCH * HID];
__device__ float g_h2[BATCH * HID];

// ---------------------------------------------------------------------------
// Kernel 1: per-batch mean over the 16 objects. 256 threads handle 4 batches
// (64 float4 lanes each).
// ---------------------------------------------------------------------------
__global__ void reduce_states_kernel(const float* __restrict__ states) {
    int lb = threadIdx.x >> 6;   // 0..3 local batch
    int d4 = threadIdx.x & 63;   // float4 index within 256-dim row
    int b  = blockIdx.x * 4 + lb;
    const float4* src = (const float4*)(states + (size_t)b * OBJ * OBS);
    float4 acc = make_float4(0.f, 0.f, 0.f, 0.f);
#pragma unroll
    for (int o = 0; o < OBJ; ++o) {
        float4 v = src[o * (OBS / 4) + d4];
        acc.x += v.x; acc.y += v.y; acc.z += v.z; acc.w += v.w;
    }
    const float inv = 1.0f / OBJ;
    acc.x *= inv; acc.y *= inv; acc.z *= inv; acc.w *= inv;
    ((float4*)(g_sbar + (size_t)b * OBS))[d4] = acc;
}

// ---------------------------------------------------------------------------
// Tiled SGEMM: C[M,N] = A[M,K] @ B[K,N] (+ epilogue per MODE)
//   MODE 1: C = relu(acc + bias[n] + (1/16)*W1full[(256 + action[m]%4)*512 + n])
//   MODE 2: C = acc + bias[n]
//   MODE 3: out[(m*16+o)*256 + n] = acc + bias[n], broadcast o=0..15
// BM=BN=64, BK=16, 256 threads, 4x4 microtile per thread.
// All dims divide tile sizes exactly for this problem; no bounds checks.
// ---------------------------------------------------------------------------
template <int MODE>
__global__ void sgemm_kernel(const float* __restrict__ A,
                             const float* __restrict__ B,
                             float* __restrict__ C,
                             int M, int N, int K,
                             const float* __restrict__ bias,
                             const float* __restrict__ W1full,
                             const int* __restrict__ action) {
    constexpr int BM = 64, BN = 64, BK = 16;
    __shared__ float As[BK][BM + 4];   // transposed A tile, padded vs conflicts
    __shared__ float Bs[BK][BN];

    const int tid = threadIdx.x;
    const int tx = tid & 15;   // 16 column groups (4 cols each)
    const int ty = tid >> 4;   // 16 row groups    (4 rows each)
    const int m0 = blockIdx.y * BM;
    const int n0 = blockIdx.x * BN;

    float acc[4][4] = {};

    for (int kt = 0; kt < K; kt += BK) {
        // Load A tile (BM x BK), store transposed As[k][m]
#pragma unroll
        for (int i = tid; i < BM * BK; i += 256) {
            int m = i >> 4;
            int k = i & 15;
            As[k][m] = A[(size_t)(m0 + m) * K + kt + k];
        }
        // Load B tile (BK x BN), row-major, coalesced
#pragma unroll
        for (int i = tid; i < BK * BN; i += 256) {
            int k = i >> 6;
            int n = i & 63;
            Bs[k][n] = B[(size_t)(kt + k) * N + n0 + n];
        }
        __syncthreads();

#pragma unroll
        for (int k = 0; k < BK; ++k) {
            float4 a4 = *(const float4*)&As[k][ty * 4];
            float4 b4 = *(const float4*)&Bs[k][tx * 4];
            float av[4] = {a4.x, a4.y, a4.z, a4.w};
            float bv[4] = {b4.x, b4.y, b4.z, b4.w};
#pragma unroll
            for (int r = 0; r < 4; ++r)
#pragma unroll
                for (int c = 0; c < 4; ++c)
                    acc[r][c] += av[r] * bv[c];
        }
        __syncthreads();
    }

    const int gm = m0 + ty * 4;
    const int gn = n0 + tx * 4;
    float4 bb = *(const float4*)(bias + gn);

    if (MODE == 1) {
#pragma unroll
        for (int r = 0; r < 4; ++r) {
            int m = gm + r;
            int j = action[m] & 3;  // action % 4 (action in [0,64))
            float4 w4 = *(const float4*)(W1full + (size_t)(256 + j) * HID + gn);
            float4 o;
            o.x = fmaxf(acc[r][0] + bb.x + 0.0625f * w4.x, 0.f);
            o.y = fmaxf(acc[r][1] + bb.y + 0.0625f * w4.y, 0.f);
            o.z = fmaxf(acc[r][2] + bb.z + 0.0625f * w4.z, 0.f);
            o.w = fmaxf(acc[r][3] + bb.w + 0.0625f * w4.w, 0.f);
            *(float4*)(C + (size_t)m * N + gn) = o;
        }
    } else if (MODE == 2) {
#pragma unroll
        for (int r = 0; r < 4; ++r) {
            float4 o;
            o.x = acc[r][0] + bb.x;
            o.y = acc[r][1] + bb.y;
            o.z = acc[r][2] + bb.z;
            o.w = acc[r][3] + bb.w;
            *(float4*)(C + (size_t)(gm + r) * N + gn) = o;
        }
    } else {  // MODE 3: broadcast across 16 objects, out row stride = 16*256
#pragma unroll
        for (int r = 0; r < 4; ++r) {
            float4 o;
            o.x = acc[r][0] + bb.x;
            o.y = acc[r][1] + bb.y;
            o.z = acc[r][2] + bb.z;
            o.w = acc[r][3] + bb.w;
            size_t base = (size_t)(gm + r) * (OBJ * OBS) + gn;
#pragma unroll
            for (int ob = 0; ob < OBJ; ++ob)
                *(float4*)(C + base + (size_t)ob * OBS) = o;
        }
    }
}

// ---------------------------------------------------------------------------
// Kernel: LayerNorm (dim 512) + ReLU in place on g_h2. One block (128 thr)
// per row; each thread owns one float4.
// ---------------------------------------------------------------------------
__device__ __forceinline__ float warp_sum(float v) {
#pragma unroll
    for (int o = 16; o > 0; o >>= 1) v += __shfl_xor_sync(0xffffffffu, v, o);
    return v;
}

__global__ void ln_relu_kernel(const float* __restrict__ g,
                               const float* __restrict__ b) {
    int row = blockIdx.x;
    int t = threadIdx.x;  // 128 threads
    float* x = g_h2 + (size_t)row * HID;
    float4 v = ((const float4*)x)[t];

    float s  = v.x + v.y + v.z + v.w;
    float ss = v.x * v.x + v.y * v.y + v.z * v.z + v.w * v.w;

    __shared__ float red[2][4];
    float sw = warp_sum(s);
    float ssw = warp_sum(ss);
    int wid = t >> 5, lid = t & 31;
    if (lid == 0) { red[0][wid] = sw; red[1][wid] = ssw; }
    __syncthreads();
    float tot_s  = red[0][0] + red[0][1] + red[0][2] + red[0][3];
    float tot_ss = red[1][0] + red[1][1] + red[1][2] + red[1][3];

    const float invn = 1.0f / HID;
    float mu = tot_s * invn;
    float var = tot_ss * invn - mu * mu;
    float rs = rsqrtf(var + 1e-5f);

    float4 gv = ((const float4*)g)[t];
    float4 bv = ((const float4*)b)[t];
    float4 o;
    o.x = fmaxf((v.x - mu) * rs * gv.x + bv.x, 0.f);
    o.y = fmaxf((v.y - mu) * rs * gv.y + bv.y, 0.f);
    o.z = fmaxf((v.z - mu) * rs * gv.z + bv.z, 0.f);
    o.w = fmaxf((v.w - mu) * rs * gv.w + bv.w, 0.f);
    ((float4*)x)[t] = o;
}

// ---------------------------------------------------------------------------
extern "C" void kernel_launch(void* const* d_in, const int* in_sizes, int n_in,
                              void* d_out, int out_size) {
    const float* states = (const float*)d_in[0];
    const int*   action = (const int*)d_in[1];
    const float* W1     = (const float*)d_in[2];
    const float* b1     = (const float*)d_in[3];
    const float* W2     = (const float*)d_in[4];
    const float* b2     = (const float*)d_in[5];
    const float* W3     = (const float*)d_in[6];
    const float* b3     = (const float*)d_in[7];
    const float* ln_g   = (const float*)d_in[8];
    const float* ln_b   = (const float*)d_in[9];
    float* out = (float*)d_out;

    float *sbar_p, *h1_p, *h2_p;
    cudaGetSymbolAddress((void**)&sbar_p, g_sbar);
    cudaGetSymbolAddress((void**)&h1_p, g_h1);
    cudaGetSymbolAddress((void**)&h2_p, g_h2);

    // 1) mean over objects
    reduce_states_kernel<<<BATCH / 4, 256>>>(states);

    // 2) h1 = relu(sbar @ W1[:256] + b1 + W1[256 + a%4] / 16)
    sgemm_kernel<1><<<dim3(HID / 64, BATCH / 64), 256>>>(
        sbar_p, W1, h1_p, BATCH, HID, OBS, b1, W1, action);

    // 3) z2 = h1 @ W2 + b2
    sgemm_kernel<2><<<dim3(HID / 64, BATCH / 64), 256>>>(
        h1_p, W2, h2_p, BATCH, HID, HID, b2, nullptr, nullptr);

    // 4) h2 = relu(LN(z2))
    ln_relu_kernel<<<BATCH, 128>>>(ln_g, ln_b);

    // 5) out = broadcast_o(h2 @ W3 + b3)
    sgemm_kernel<3><<<dim3(OBS / 64, BATCH / 64), 256>>>(
        h2_p, W3, out, BATCH, OBS, HID, b3, nullptr, nullptr);
}

// round 3
// speedup vs baseline: 1.4460x; 1.4460x over previous
#include <cuda_runtime.h>
#include <cuda_bf16.h>
#include <cstdint>
#include <math.h>

#define BATCH 4096
#define OBJ   16
#define OBS   256
#define HID   512

// tcgen05 is an arch-accelerated feature: only available when compiling the
// sm_103a-specific target. The harness also runs a plain compute_103 PTX pass
// where these instructions are illegal, so everything tcgen05 is guarded and
// a correct FFMA fallback is supplied for that pass.
#if defined(__CUDA_ARCH__) && (defined(__CUDA_ARCH_FEAT_SM103_ALL) || \
    (defined(__CUDA_ARCH_SPECIFIC__) && __CUDA_ARCH_SPECIFIC__ == 1030) || \
    (defined(__CUDA_ARCH_FAMILY_SPECIFIC__) && __CUDA_ARCH_FAMILY_SPECIFIC__ == 1030))
#define HAS_TCGEN05 1
#else
#define HAS_TCGEN05 0
#endif

// ---------------------------------------------------------------------------
// Scratch (device globals; no allocation allowed)
// ---------------------------------------------------------------------------
__device__ __nv_bfloat16 g_sbar_h[BATCH * OBS], g_sbar_l[BATCH * OBS];
__device__ __nv_bfloat16 g_h1_h[BATCH * HID], g_h1_l[BATCH * HID];
__device__ float         g_z2[BATCH * HID];
__device__ __nv_bfloat16 g_h2_h[BATCH * HID], g_h2_l[BATCH * HID];
__device__ __nv_bfloat16 g_W1T_h[HID * OBS], g_W1T_l[HID * OBS];   // [512][256]
__device__ __nv_bfloat16 g_W2T_h[HID * HID], g_W2T_l[HID * HID];   // [512][512]
__device__ __nv_bfloat16 g_W3T_h[OBS * HID], g_W3T_l[OBS * HID];   // [256][512]

// ---------------------------------------------------------------------------
// helpers
// ---------------------------------------------------------------------------
__device__ __forceinline__ uint32_t smem_u32(const void* p) {
    uint32_t a;
    asm("{ .reg .u64 t; cvta.to.shared.u64 t, %1; cvt.u32.u64 %0, t; }"
        : "=r"(a) : "l"(p));
    return a;
}
__device__ __forceinline__ uint32_t sw128(uint32_t off) {
    return off ^ ((off >> 3) & 0x70);
}
__device__ __forceinline__ void split_bf16(float v, __nv_bfloat16& hi, __nv_bfloat16& lo) {
    hi = __float2bfloat16(v);
    lo = __float2bfloat16(v - __bfloat162float(hi));
}

#if HAS_TCGEN05
__device__ __forceinline__ uint32_t elect_one() {
    uint32_t pred;
    asm volatile("{\n\t.reg .pred p;\n\telect.sync _|p, 0xFFFFFFFF;\n\t"
                 "selp.b32 %0, 1, 0, p;\n\t}" : "=r"(pred));
    return pred;
}

#define TCGEN05_ALLOC(sm_addr, ncols)                                          \
    asm volatile("tcgen05.alloc.cta_group::1.sync.aligned.shared::cta.b32 [%0], %1;" \
                 :: "r"((uint32_t)(sm_addr)), "r"((uint32_t)(ncols)) : "memory")
#define TCGEN05_DEALLOC(tmem, ncols)                                           \
    asm volatile("tcgen05.dealloc.cta_group::1.sync.aligned.b32 %0, %1;"       \
                 :: "r"(tmem), "r"((uint32_t)(ncols)))
#define TCGEN05_RELINQ()                                                       \
    asm volatile("tcgen05.relinquish_alloc_permit.cta_group::1.sync.aligned;")
#define TCGEN05_COMMIT(mbar)                                                   \
    asm volatile("tcgen05.commit.cta_group::1.mbarrier::arrive::one.shared::cluster.b64 [%0];" \
                 :: "r"((uint32_t)(mbar)) : "memory")
#define TCGEN05_WAIT_LD() asm volatile("tcgen05.wait::ld.sync.aligned;" ::: "memory")
#define TCGEN05_FENCE_AFTER() asm volatile("tcgen05.fence::after_thread_sync;" ::: "memory")
#define FENCE_ASYNC_SHARED() asm volatile("fence.proxy.async.shared::cta;" ::: "memory")

#define MBARRIER_INIT(mbar, cnt)                                               \
    asm volatile("mbarrier.init.shared.b64 [%0], %1;"                          \
                 :: "r"((uint32_t)(mbar)), "r"((uint32_t)(cnt)) : "memory")
#define MBARRIER_WAIT_PARITY(mbar_a, par_a) do {                               \
    uint32_t _mb = (uint32_t)(mbar_a);                                         \
    uint32_t _pa = (uint32_t)(par_a);                                          \
    uint32_t _done;                                                            \
    asm volatile("{\n\t.reg .pred p;\n\t"                                      \
        "mbarrier.try_wait.parity.acquire.cta.shared::cta.b64 p, [%1], %2;\n\t"\
        "selp.b32 %0, 1, 0, p;\n\t}"                                           \
        : "=r"(_done) : "r"(_mb), "r"(_pa) : "memory");                        \
    if (!_done) {                                                              \
        asm volatile("{\n\t.reg .pred P1;\n\t"                                 \
            "WL_%=:\n\t"                                                       \
            "mbarrier.try_wait.parity.acquire.cta.shared::cta.b64 P1, [%0], %1, 0x989680;\n\t" \
            "@P1 bra.uni WD_%=;\n\t"                                           \
            "bra.uni WL_%=;\n\t"                                               \
            "WD_%=:\n\t}" :: "r"(_mb), "r"(_pa) : "memory");                   \
    }                                                                          \
} while (0)

#define TCGEN05_LD_X32(r, tmem_addr)                                           \
    asm volatile("tcgen05.ld.sync.aligned.32x32b.x32.b32 "                     \
        "{%0, %1, %2, %3, %4, %5, %6, %7, "                                    \
        " %8, %9, %10, %11, %12, %13, %14, %15, "                              \
        " %16, %17, %18, %19, %20, %21, %22, %23, "                            \
        " %24, %25, %26, %27, %28, %29, %30, %31}, [%32];"                     \
        : "=r"((r)[0]),  "=r"((r)[1]),  "=r"((r)[2]),  "=r"((r)[3]),           \
          "=r"((r)[4]),  "=r"((r)[5]),  "=r"((r)[6]),  "=r"((r)[7]),           \
          "=r"((r)[8]),  "=r"((r)[9]),  "=r"((r)[10]), "=r"((r)[11]),          \
          "=r"((r)[12]), "=r"((r)[13]), "=r"((r)[14]), "=r"((r)[15]),          \
          "=r"((r)[16]), "=r"((r)[17]), "=r"((r)[18]), "=r"((r)[19]),          \
          "=r"((r)[20]), "=r"((r)[21]), "=r"((r)[22]), "=r"((r)[23]),          \
          "=r"((r)[24]), "=r"((r)[25]), "=r"((r)[26]), "=r"((r)[27]),          \
          "=r"((r)[28]), "=r"((r)[29]), "=r"((r)[30]), "=r"((r)[31])           \
        : "r"(tmem_addr))

// SS bf16 MMA, cta_group::1, fp32 accumulate in TMEM
__device__ __forceinline__ void mma_bf16_ss(uint32_t d, uint64_t a, uint64_t b,
                                            uint32_t idesc, uint32_t en) {
    asm volatile(
        "{\n\t.reg .pred p;\n\tsetp.ne.u32 p, %4, 0;\n\t"
        "tcgen05.mma.cta_group::1.kind::f16 [%0], %1, %2, %3, {%5, %5, %5, %5}, p;\n\t}"
        :: "r"(d), "l"(a), "l"(b), "r"(idesc), "r"(en), "r"(0u) : "memory");
}

// SW128 descriptor base: layout=SW128(2), version=1, SBO=64 (1024B), LBO=1 (16B)
__device__ __forceinline__ uint64_t make_desc(uint32_t addr) {
    return ((uint64_t)2 << 61) | ((uint64_t)1 << 46) | ((uint64_t)64 << 32) |
           ((uint64_t)1 << 16) | ((uint64_t)(addr >> 4) & 0x3FFF);
}

// idesc: dtype F32 (bit4), atype BF16 (bit7), btype BF16 (bit10),
// N=128 -> (128/8)<<17, M=128 -> (128/16)<<24
static constexpr uint32_t IDESC_128x128 = 0x8200490u;
#endif  // HAS_TCGEN05

// ---------------------------------------------------------------------------
// Kernel: transpose + bf16-split the three weight matrices.
// ---------------------------------------------------------------------------
__global__ void tconv_kernel(const float* __restrict__ W1,
                             const float* __restrict__ W2,
                             const float* __restrict__ W3) {
    const float* W; __nv_bfloat16 *Th, *Tl; int K, N;
    if (blockIdx.z == 0)      { W = W1; Th = g_W1T_h; Tl = g_W1T_l; K = OBS; N = HID; }
    else if (blockIdx.z == 1) { W = W2; Th = g_W2T_h; Tl = g_W2T_l; K = HID; N = HID; }
    else                      { W = W3; Th = g_W3T_h; Tl = g_W3T_l; K = HID; N = OBS; }
    int k0 = blockIdx.y * 32, n0 = blockIdx.x * 32;
    if (k0 >= K || n0 >= N) return;
    __shared__ float t[32][33];
#pragma unroll
    for (int i = 0; i < 4; ++i)
        t[threadIdx.y + i * 8][threadIdx.x] =
            W[(size_t)(k0 + threadIdx.y + i * 8) * N + n0 + threadIdx.x];
    __syncthreads();
#pragma unroll
    for (int i = 0; i < 4; ++i) {
        int n = threadIdx.y + i * 8;
        float v = t[threadIdx.x][n];
        __nv_bfloat16 hi, lo; split_bf16(v, hi, lo);
        size_t o = (size_t)(n0 + n) * K + k0 + threadIdx.x;
        Th[o] = hi; Tl[o] = lo;
    }
}

// ---------------------------------------------------------------------------
// Kernel: per-batch mean over 16 objects -> bf16 hi/lo
// ---------------------------------------------------------------------------
__global__ void reduce_states_kernel(const float* __restrict__ states) {
    int lb = threadIdx.x >> 6;
    int d4 = threadIdx.x & 63;
    int b  = blockIdx.x * 4 + lb;
    const float4* src = (const float4*)(states + (size_t)b * OBJ * OBS);
    float4 acc = make_float4(0.f, 0.f, 0.f, 0.f);
#pragma unroll
    for (int o = 0; o < OBJ; ++o) {
        float4 v = src[o * (OBS / 4) + d4];
        acc.x += v.x; acc.y += v.y; acc.z += v.z; acc.w += v.w;
    }
    const float inv = 1.0f / OBJ;
    float vals[4] = {acc.x * inv, acc.y * inv, acc.z * inv, acc.w * inv};
    size_t base = (size_t)b * OBS + d4 * 4;
#pragma unroll
    for (int c = 0; c < 4; ++c) {
        __nv_bfloat16 hi, lo; split_bf16(vals[c], hi, lo);
        g_sbar_h[base + c] = hi; g_sbar_l[base + c] = lo;
    }
}

// ---------------------------------------------------------------------------
// tcgen05 bf16-split GEMM: D[128,128] tile of A[M,K] @ B[K,N] (B given as
// BT[N][K] hi/lo). 3 MMA products per K-step: Ah*Bh + Ah*Bl + Al*Bh.
// MODE 1: h1 = relu(D + b1[n] + W1[256+action[m]%4][n]/16) -> bf16 hi/lo
// MODE 2: z2 = D + b2[n] -> fp32
// MODE 3: out[(m*16+ob)*256 + n] = D + b3[n], ob = 0..15 -> fp32
// ---------------------------------------------------------------------------
static constexpr int SM_TMEMPTR = 0;
static constexpr int SM_MBAR    = 8;     // two 8B mbarriers at 8, 16
static constexpr int SM_BIAS    = 64;    // 128 floats
static constexpr int SM_W1ROWS  = 576;   // 4 x 128 floats (MODE 1)
static constexpr int SM_TILES   = 4096;  // 8 tiles x 16KB = 128KB
static constexpr int TILE_BYTES = 128 * 128;
static constexpr int GEMM_SMEM  = SM_TILES + 8 * TILE_BYTES;  // 135168

template <int MODE>
__global__ __launch_bounds__(256, 1)
void gemm_bf16s_kernel(const __nv_bfloat16* __restrict__ Ah,
                       const __nv_bfloat16* __restrict__ Al,
                       const __nv_bfloat16* __restrict__ BTh,
                       const __nv_bfloat16* __restrict__ BTl,
                       int Ktot, int Ntot,
                       const float* __restrict__ bias,
                       const int* __restrict__ action,
                       const float* __restrict__ W1,
                       float* __restrict__ outf,
                       __nv_bfloat16* __restrict__ outh,
                       __nv_bfloat16* __restrict__ outl) {
#if HAS_TCGEN05
    extern __shared__ char sm[];
    const uint32_t smb = smem_u32(sm);
    const int tid = threadIdx.x;
    const int wid = tid >> 5;
    const int lid = tid & 31;
    const int m0 = blockIdx.y * 128;
    const int n0 = blockIdx.x * 128;

    float* s_bias = (float*)(sm + SM_BIAS);
    float* s_w1   = (float*)(sm + SM_W1ROWS);

    if (wid == 0) TCGEN05_ALLOC(smb + SM_TMEMPTR, 128);
    if (tid == 0) {
        MBARRIER_INIT(smb + SM_MBAR, 1);
        MBARRIER_INIT(smb + SM_MBAR + 8, 1);
    }
    if (tid < 128) s_bias[tid] = bias[n0 + tid];
    if (MODE == 1) {
        for (int idx = tid; idx < 512; idx += 256)
            s_w1[idx] = W1[(size_t)(256 + (idx >> 7)) * HID + n0 + (idx & 127)];
    }
    __syncthreads();
    uint32_t tmem;
    asm volatile("ld.shared.b32 %0, [%1];" : "=r"(tmem) : "r"(smb + SM_TMEMPTR));

    const __nv_bfloat16* srcs[4] = {Ah, Al, BTh, BTl};
    const int row0s[4] = {m0, m0, n0, n0};

    const int NC = Ktot >> 6;  // chunks of 64 K
    int ph0 = 0, ph1 = 0;

    for (int i = 0; i < NC; ++i) {
        const int buf = i & 1;
        if (i >= 2) {
            if (buf == 0) { MBARRIER_WAIT_PARITY(smb + SM_MBAR, ph0); ph0 ^= 1; }
            else          { MBARRIER_WAIT_PARITY(smb + SM_MBAR + 8, ph1); ph1 ^= 1; }
        }
        const int kt = i << 6;
        // fill 4 tiles: [128 rows][64 bf16] = [128][128B], SW128 swizzled
#pragma unroll
        for (int t = 0; t < 4; ++t) {
            char* st = sm + SM_TILES + (buf * 4 + t) * TILE_BYTES;
            const __nv_bfloat16* g = srcs[t];
            const int r0 = row0s[t];
            for (int idx = tid; idx < 128 * 8; idx += 256) {
                int r = idx >> 3, q = idx & 7;
                uint4 v = *(const uint4*)(g + (size_t)(r0 + r) * Ktot + kt + q * 8);
                *(uint4*)(st + sw128(r * 128 + q * 16)) = v;
            }
        }
        FENCE_ASYNC_SHARED();
        __syncthreads();
        if (wid == 0 && elect_one()) {
            uint32_t base = smb + SM_TILES + buf * 4 * TILE_BYTES;
            uint64_t dAh = make_desc(base);
            uint64_t dAl = make_desc(base + TILE_BYTES);
            uint64_t dBh = make_desc(base + 2 * TILE_BYTES);
            uint64_t dBl = make_desc(base + 3 * TILE_BYTES);
#pragma unroll
            for (int ks = 0; ks < 4; ++ks) {
                mma_bf16_ss(tmem, dAh + ks * 2, dBh + ks * 2, IDESC_128x128,
                            (i > 0 || ks > 0) ? 1u : 0u);
                mma_bf16_ss(tmem, dAh + ks * 2, dBl + ks * 2, IDESC_128x128, 1u);
                mma_bf16_ss(tmem, dAl + ks * 2, dBh + ks * 2, IDESC_128x128, 1u);
            }
            TCGEN05_COMMIT(smb + SM_MBAR + buf * 8);
        }
    }
    MBARRIER_WAIT_PARITY(smb + SM_MBAR, ph0);
    MBARRIER_WAIT_PARITY(smb + SM_MBAR + 8, ph1);
    TCGEN05_FENCE_AFTER();

    // ------------------------- epilogue -------------------------
    const int wq = wid & 3, wc = wid >> 2;
    const int m = m0 + wq * 32 + lid;
    int jrow = 0;
    if (MODE == 1) jrow = (action[m] & 3) * 128;

#pragma unroll
    for (int cc = 0; cc < 2; ++cc) {
        const int cb = wc * 64 + cc * 32;
        uint32_t d[32];
        TCGEN05_LD_X32(d, tmem + cb);
        TCGEN05_WAIT_LD();
        float vals[32];
#pragma unroll
        for (int c = 0; c < 32; ++c)
            vals[c] = __uint_as_float(d[c]) + s_bias[cb + c];

        if (MODE == 1) {
            uint32_t ph[16], pl[16];
#pragma unroll
            for (int c = 0; c < 32; c += 2) {
                float v0 = fmaxf(vals[c] + 0.0625f * s_w1[jrow + cb + c], 0.f);
                float v1 = fmaxf(vals[c + 1] + 0.0625f * s_w1[jrow + cb + c + 1], 0.f);
                __nv_bfloat16 h0, l0, h1x, l1; split_bf16(v0, h0, l0); split_bf16(v1, h1x, l1);
                __nv_bfloat162 hp(h0, h1x), lp(l0, l1);
                ph[c >> 1] = *(uint32_t*)&hp;
                pl[c >> 1] = *(uint32_t*)&lp;
            }
            size_t o = (size_t)m * Ntot + n0 + cb;
#pragma unroll
            for (int q = 0; q < 4; ++q) {
                *(uint4*)(outh + o + q * 8) = *(uint4*)&ph[q * 4];
                *(uint4*)(outl + o + q * 8) = *(uint4*)&pl[q * 4];
            }
        } else if (MODE == 2) {
            size_t o = (size_t)m * Ntot + n0 + cb;
#pragma unroll
            for (int q = 0; q < 8; ++q)
                *(float4*)(outf + o + q * 4) = *(float4*)&vals[q * 4];
        } else {
            size_t base = (size_t)m * (OBJ * OBS) + n0 + cb;
#pragma unroll
            for (int ob = 0; ob < OBJ; ++ob) {
#pragma unroll
                for (int q = 0; q < 8; ++q)
                    *(float4*)(outf + base + (size_t)ob * OBS + q * 4) = *(float4*)&vals[q * 4];
            }
        }
    }

    __syncthreads();
    if (wid == 0) {
        TCGEN05_RELINQ();
        TCGEN05_DEALLOC(tmem, 128);
    }
#else
    // Fallback (non-sm_103a PTX pass): plain FFMA, correct but slow. The GB300
    // driver selects the exact-match sm_103a cubin, so this does not run there.
    const int tid = threadIdx.x;
    const int m0 = blockIdx.y * 128;
    const int n0 = blockIdx.x * 128;
    for (int e = tid; e < 128 * 128; e += 256) {
        int r = e >> 7, c = e & 127;
        int m = m0 + r, n = n0 + c;
        float acc = 0.f;
        for (int k = 0; k < Ktot; ++k) {
            float a = __bfloat162float(Ah[(size_t)m * Ktot + k]) +
                      __bfloat162float(Al[(size_t)m * Ktot + k]);
            float b = __bfloat162float(BTh[(size_t)n * Ktot + k]) +
                      __bfloat162float(BTl[(size_t)n * Ktot + k]);
            acc += a * b;
        }
        acc += bias[n];
        if (MODE == 1) {
            int j = action[m] & 3;
            float v = fmaxf(acc + 0.0625f * W1[(size_t)(256 + j) * HID + n], 0.f);
            __nv_bfloat16 hi, lo; split_bf16(v, hi, lo);
            outh[(size_t)m * Ntot + n] = hi;
            outl[(size_t)m * Ntot + n] = lo;
        } else if (MODE == 2) {
            outf[(size_t)m * Ntot + n] = acc;
        } else {
            size_t base = (size_t)m * (OBJ * OBS) + n;
            for (int ob = 0; ob < OBJ; ++ob) outf[base + (size_t)ob * OBS] = acc;
        }
    }
#endif
}

// ---------------------------------------------------------------------------
// LayerNorm(512) + ReLU on g_z2 -> bf16 hi/lo
// ---------------------------------------------------------------------------
__device__ __forceinline__ float warp_sum(float v) {
#pragma unroll
    for (int o = 16; o > 0; o >>= 1) v += __shfl_xor_sync(0xffffffffu, v, o);
    return v;
}

__global__ void ln_relu_kernel(const float* __restrict__ g,
                               const float* __restrict__ b) {
    int row = blockIdx.x;
    int t = threadIdx.x;  // 128
    const float* x = g_z2 + (size_t)row * HID;
    float4 v = ((const float4*)x)[t];
    float s  = v.x + v.y + v.z + v.w;
    float ss = v.x * v.x + v.y * v.y + v.z * v.z + v.w * v.w;
    __shared__ float red[2][4];
    float sw = warp_sum(s), ssw = warp_sum(ss);
    int wid = t >> 5, lid = t & 31;
    if (lid == 0) { red[0][wid] = sw; red[1][wid] = ssw; }
    __syncthreads();
    float ts  = red[0][0] + red[0][1] + red[0][2] + red[0][3];
    float tss = red[1][0] + red[1][1] + red[1][2] + red[1][3];
    const float invn = 1.0f / HID;
    float mu = ts * invn;
    float var = tss * invn - mu * mu;
    float rs = rsqrtf(var + 1e-5f);
    float4 gv = ((const float4*)g)[t];
    float4 bv = ((const float4*)b)[t];
    float vals[4];
    vals[0] = fmaxf((v.x - mu) * rs * gv.x + bv.x, 0.f);
    vals[1] = fmaxf((v.y - mu) * rs * gv.y + bv.y, 0.f);
    vals[2] = fmaxf((v.z - mu) * rs * gv.z + bv.z, 0.f);
    vals[3] = fmaxf((v.w - mu) * rs * gv.w + bv.w, 0.f);
    size_t base = (size_t)row * HID + t * 4;
    __nv_bfloat16 h0, l0, h1, l1;
    split_bf16(vals[0], h0, l0); split_bf16(vals[1], h1, l1);
    *(__nv_bfloat162*)(g_h2_h + base) = __nv_bfloat162(h0, h1);
    *(__nv_bfloat162*)(g_h2_l + base) = __nv_bfloat162(l0, l1);
    split_bf16(vals[2], h0, l0); split_bf16(vals[3], h1, l1);
    *(__nv_bfloat162*)(g_h2_h + base + 2) = __nv_bfloat162(h0, h1);
    *(__nv_bfloat162*)(g_h2_l + base + 2) = __nv_bfloat162(l0, l1);
}

// ---------------------------------------------------------------------------
extern "C" void kernel_launch(void* const* d_in, const int* in_sizes, int n_in,
                              void* d_out, int out_size) {
    const float* states = (const float*)d_in[0];
    const int*   action = (const int*)d_in[1];
    const float* W1     = (const float*)d_in[2];
    const float* b1     = (const float*)d_in[3];
    const float* W2     = (const float*)d_in[4];
    const float* b2     = (const float*)d_in[5];
    const float* W3     = (const float*)d_in[6];
    const float* b3     = (const float*)d_in[7];
    const float* ln_g   = (const float*)d_in[8];
    const float* ln_b   = (const float*)d_in[9];
    float* out = (float*)d_out;

    __nv_bfloat16 *sbh, *sbl, *h1h, *h1l, *h2h, *h2l;
    __nv_bfloat16 *w1h, *w1l, *w2h, *w2l, *w3h, *w3l;
    float* z2p;
    cudaGetSymbolAddress((void**)&sbh, g_sbar_h);
    cudaGetSymbolAddress((void**)&sbl, g_sbar_l);
    cudaGetSymbolAddress((void**)&h1h, g_h1_h);
    cudaGetSymbolAddress((void**)&h1l, g_h1_l);
    cudaGetSymbolAddress((void**)&h2h, g_h2_h);
    cudaGetSymbolAddress((void**)&h2l, g_h2_l);
    cudaGetSymbolAddress((void**)&w1h, g_W1T_h);
    cudaGetSymbolAddress((void**)&w1l, g_W1T_l);
    cudaGetSymbolAddress((void**)&w2h, g_W2T_h);
    cudaGetSymbolAddress((void**)&w2l, g_W2T_l);
    cudaGetSymbolAddress((void**)&w3h, g_W3T_h);
    cudaGetSymbolAddress((void**)&w3l, g_W3T_l);
    cudaGetSymbolAddress((void**)&z2p, g_z2);

    cudaFuncSetAttribute(gemm_bf16s_kernel<1>,
                         cudaFuncAttributeMaxDynamicSharedMemorySize, GEMM_SMEM);
    cudaFuncSetAttribute(gemm_bf16s_kernel<2>,
                         cudaFuncAttributeMaxDynamicSharedMemorySize, GEMM_SMEM);
    cudaFuncSetAttribute(gemm_bf16s_kernel<3>,
                         cudaFuncAttributeMaxDynamicSharedMemorySize, GEMM_SMEM);

    // 0) transpose + split weights
    tconv_kernel<<<dim3(16, 16, 3), dim3(32, 8)>>>(W1, W2, W3);
    // 1) mean over objects -> sbar hi/lo
    reduce_states_kernel<<<BATCH / 4, 256>>>(states);
    // 2) h1 = relu(sbar @ W1[:256] + b1 + W1[256+a%4]/16) -> bf16 hi/lo
    gemm_bf16s_kernel<1><<<dim3(HID / 128, BATCH / 128), 256, GEMM_SMEM>>>(
        sbh, sbl, w1h, w1l, OBS, HID, b1, action, W1, nullptr, h1h, h1l);
    // 3) z2 = h1 @ W2 + b2 -> fp32
    gemm_bf16s_kernel<2><<<dim3(HID / 128, BATCH / 128), 256, GEMM_SMEM>>>(
        h1h, h1l, w2h, w2l, HID, HID, b2, nullptr, nullptr, z2p, nullptr, nullptr);
    // 4) h2 = relu(LN(z2)) -> bf16 hi/lo
    ln_relu_kernel<<<BATCH, 128>>>(ln_g, ln_b);
    // 5) out = broadcast_obj(h2 @ W3 + b3)
    gemm_bf16s_kernel<3><<<dim3(OBS / 128, BATCH / 128), 256, GEMM_SMEM>>>(
        h2h, h2l, w3h, w3l, HID, OBS, b3, nullptr, nullptr, out, nullptr, nullptr);
}

// round 4
// speedup vs baseline: 2.6046x; 1.8012x over previous
#include <cuda_runtime.h>
#include <cuda_bf16.h>
#include <cstdint>
#include <math.h>

#define BATCH 4096
#define OBJ   16
#define OBS   256
#define HID   512

#if defined(__CUDA_ARCH__) && (defined(__CUDA_ARCH_FEAT_SM103_ALL) || \
    (defined(__CUDA_ARCH_SPECIFIC__) && __CUDA_ARCH_SPECIFIC__ == 1030) || \
    (defined(__CUDA_ARCH_FAMILY_SPECIFIC__) && __CUDA_ARCH_FAMILY_SPECIFIC__ == 1030))
#define HAS_TCGEN05 1
#else
#define HAS_TCGEN05 0
#endif

// ---------------------------------------------------------------------------
// Scratch
// ---------------------------------------------------------------------------
__device__ __nv_bfloat16 g_sbar_h[BATCH * OBS], g_sbar_l[BATCH * OBS];
__device__ __nv_bfloat16 g_h1_h[BATCH * HID], g_h1_l[BATCH * HID];
__device__ float         g_z2[BATCH * HID];
__device__ __nv_bfloat16 g_h2_h[BATCH * HID], g_h2_l[BATCH * HID];
__device__ __nv_bfloat16 g_W1T_h[HID * OBS], g_W1T_l[HID * OBS];
__device__ __nv_bfloat16 g_W2T_h[HID * HID], g_W2T_l[HID * HID];
__device__ __nv_bfloat16 g_W3T_h[OBS * HID], g_W3T_l[OBS * HID];

// ---------------------------------------------------------------------------
// helpers
// ---------------------------------------------------------------------------
__device__ __forceinline__ uint32_t smem_u32(const void* p) {
    uint32_t a;
    asm("{ .reg .u64 t; cvta.to.shared.u64 t, %1; cvt.u32.u64 %0, t; }"
        : "=r"(a) : "l"(p));
    return a;
}
__device__ __forceinline__ uint32_t sw128(uint32_t off) {
    return off ^ ((off >> 3) & 0x70);
}
__device__ __forceinline__ void split_bf16(float v, __nv_bfloat16& hi, __nv_bfloat16& lo) {
    hi = __float2bfloat16(v);
    lo = __float2bfloat16(v - __bfloat162float(hi));
}

#define CP_ASYNC16(smem_a, gptr)                                               \
    asm volatile("cp.async.cg.shared.global [%0], [%1], 16;"                   \
                 :: "r"((uint32_t)(smem_a)), "l"(gptr) : "memory")
#define CP_COMMIT() asm volatile("cp.async.commit_group;" ::: "memory")
#define CP_WAIT1()  asm volatile("cp.async.wait_group 1;" ::: "memory")

#if HAS_TCGEN05
__device__ __forceinline__ uint32_t elect_one() {
    uint32_t pred;
    asm volatile("{\n\t.reg .pred p;\n\telect.sync _|p, 0xFFFFFFFF;\n\t"
                 "selp.b32 %0, 1, 0, p;\n\t}" : "=r"(pred));
    return pred;
}
#define TCGEN05_ALLOC(sm_addr, ncols)                                          \
    asm volatile("tcgen05.alloc.cta_group::1.sync.aligned.shared::cta.b32 [%0], %1;" \
                 :: "r"((uint32_t)(sm_addr)), "r"((uint32_t)(ncols)) : "memory")
#define TCGEN05_DEALLOC(tmem, ncols)                                           \
    asm volatile("tcgen05.dealloc.cta_group::1.sync.aligned.b32 %0, %1;"       \
                 :: "r"(tmem), "r"((uint32_t)(ncols)))
#define TCGEN05_RELINQ()                                                       \
    asm volatile("tcgen05.relinquish_alloc_permit.cta_group::1.sync.aligned;")
#define TCGEN05_COMMIT(mbar)                                                   \
    asm volatile("tcgen05.commit.cta_group::1.mbarrier::arrive::one.shared::cluster.b64 [%0];" \
                 :: "r"((uint32_t)(mbar)) : "memory")
#define TCGEN05_WAIT_LD() asm volatile("tcgen05.wait::ld.sync.aligned;" ::: "memory")
#define TCGEN05_FENCE_AFTER() asm volatile("tcgen05.fence::after_thread_sync;" ::: "memory")
#define FENCE_ASYNC_SHARED() asm volatile("fence.proxy.async.shared::cta;" ::: "memory")

#define MBARRIER_INIT(mbar, cnt)                                               \
    asm volatile("mbarrier.init.shared.b64 [%0], %1;"                          \
                 :: "r"((uint32_t)(mbar)), "r"((uint32_t)(cnt)) : "memory")
#define MBARRIER_WAIT_PARITY(mbar_a, par_a) do {                               \
    uint32_t _mb = (uint32_t)(mbar_a);                                         \
    uint32_t _pa = (uint32_t)(par_a);                                          \
    uint32_t _done;                                                            \
    asm volatile("{\n\t.reg .pred p;\n\t"                                      \
        "mbarrier.try_wait.parity.acquire.cta.shared::cta.b64 p, [%1], %2;\n\t"\
        "selp.b32 %0, 1, 0, p;\n\t}"                                           \
        : "=r"(_done) : "r"(_mb), "r"(_pa) : "memory");                        \
    if (!_done) {                                                              \
        asm volatile("{\n\t.reg .pred P1;\n\t"                                 \
            "WL_%=:\n\t"                                                       \
            "mbarrier.try_wait.parity.acquire.cta.shared::cta.b64 P1, [%0], %1, 0x989680;\n\t" \
            "@P1 bra.uni WD_%=;\n\t"                                           \
            "bra.uni WL_%=;\n\t"                                               \
            "WD_%=:\n\t}" :: "r"(_mb), "r"(_pa) : "memory");                   \
    }                                                                          \
} while (0)

#define TCGEN05_LD_X32(r, tmem_addr)                                           \
    asm volatile("tcgen05.ld.sync.aligned.32x32b.x32.b32 "                     \
        "{%0, %1, %2, %3, %4, %5, %6, %7, "                                    \
        " %8, %9, %10, %11, %12, %13, %14, %15, "                              \
        " %16, %17, %18, %19, %20, %21, %22, %23, "                            \
        " %24, %25, %26, %27, %28, %29, %30, %31}, [%32];"                     \
        : "=r"((r)[0]),  "=r"((r)[1]),  "=r"((r)[2]),  "=r"((r)[3]),           \
          "=r"((r)[4]),  "=r"((r)[5]),  "=r"((r)[6]),  "=r"((r)[7]),           \
          "=r"((r)[8]),  "=r"((r)[9]),  "=r"((r)[10]), "=r"((r)[11]),          \
          "=r"((r)[12]), "=r"((r)[13]), "=r"((r)[14]), "=r"((r)[15]),          \
          "=r"((r)[16]), "=r"((r)[17]), "=r"((r)[18]), "=r"((r)[19]),          \
          "=r"((r)[20]), "=r"((r)[21]), "=r"((r)[22]), "=r"((r)[23]),          \
          "=r"((r)[24]), "=r"((r)[25]), "=r"((r)[26]), "=r"((r)[27]),          \
          "=r"((r)[28]), "=r"((r)[29]), "=r"((r)[30]), "=r"((r)[31])           \
        : "r"(tmem_addr))

__device__ __forceinline__ void mma_bf16_ss(uint32_t d, uint64_t a, uint64_t b,
                                            uint32_t idesc, uint32_t en) {
    asm volatile(
        "{\n\t.reg .pred p;\n\tsetp.ne.u32 p, %4, 0;\n\t"
        "tcgen05.mma.cta_group::1.kind::f16 [%0], %1, %2, %3, {%5, %5, %5, %5}, p;\n\t}"
        :: "r"(d), "l"(a), "l"(b), "r"(idesc), "r"(en), "r"(0u) : "memory");
}
__device__ __forceinline__ uint64_t make_desc(uint32_t addr) {
    return ((uint64_t)2 << 61) | ((uint64_t)1 << 46) | ((uint64_t)64 << 32) |
           ((uint64_t)1 << 16) | ((uint64_t)(addr >> 4) & 0x3FFF);
}
static constexpr uint32_t IDESC_128x128 = 0x8200490u;
#endif  // HAS_TCGEN05

// ---------------------------------------------------------------------------
// transpose + bf16-split weights
// ---------------------------------------------------------------------------
__global__ void tconv_kernel(const float* __restrict__ W1,
                             const float* __restrict__ W2,
                             const float* __restrict__ W3) {
    const float* W; __nv_bfloat16 *Th, *Tl; int K, N;
    if (blockIdx.z == 0)      { W = W1; Th = g_W1T_h; Tl = g_W1T_l; K = OBS; N = HID; }
    else if (blockIdx.z == 1) { W = W2; Th = g_W2T_h; Tl = g_W2T_l; K = HID; N = HID; }
    else                      { W = W3; Th = g_W3T_h; Tl = g_W3T_l; K = HID; N = OBS; }
    int k0 = blockIdx.y * 32, n0 = blockIdx.x * 32;
    if (k0 >= K || n0 >= N) return;
    __shared__ float t[32][33];
#pragma unroll
    for (int i = 0; i < 4; ++i)
        t[threadIdx.y + i * 8][threadIdx.x] =
            W[(size_t)(k0 + threadIdx.y + i * 8) * N + n0 + threadIdx.x];
    __syncthreads();
#pragma unroll
    for (int i = 0; i < 4; ++i) {
        int n = threadIdx.y + i * 8;
        float v = t[threadIdx.x][n];
        __nv_bfloat16 hi, lo; split_bf16(v, hi, lo);
        size_t o = (size_t)(n0 + n) * K + k0 + threadIdx.x;
        Th[o] = hi; Tl[o] = lo;
    }
}

// ---------------------------------------------------------------------------
// per-batch mean over 16 objects -> bf16 hi/lo
// ---------------------------------------------------------------------------
__global__ void reduce_states_kernel(const float* __restrict__ states) {
    int lb = threadIdx.x >> 6;
    int d4 = threadIdx.x & 63;
    int b  = blockIdx.x * 4 + lb;
    const float4* src = (const float4*)(states + (size_t)b * OBJ * OBS);
    float4 acc = make_float4(0.f, 0.f, 0.f, 0.f);
#pragma unroll
    for (int o = 0; o < OBJ; ++o) {
        float4 v = src[o * (OBS / 4) + d4];
        acc.x += v.x; acc.y += v.y; acc.z += v.z; acc.w += v.w;
    }
    const float inv = 1.0f / OBJ;
    float vals[4] = {acc.x * inv, acc.y * inv, acc.z * inv, acc.w * inv};
    size_t base = (size_t)b * OBS + d4 * 4;
#pragma unroll
    for (int c = 0; c < 4; ++c) {
        __nv_bfloat16 hi, lo; split_bf16(vals[c], hi, lo);
        g_sbar_h[base + c] = hi; g_sbar_l[base + c] = lo;
    }
}

// ---------------------------------------------------------------------------
// tcgen05 bf16-split GEMM with 3-stage cp.async pipeline.
// MODE 1: h1 = relu(D + b1 + W1row/16) -> bf16 hi/lo
// MODE 2: z2 = D + b2 -> fp32
// MODE 3: out[(m*16+ob0+j)*256+n] = D + b3, j=0..nob-1
// ---------------------------------------------------------------------------
static constexpr int SM_TMEMPTR = 0;
static constexpr int SM_MBAR    = 8;     // three 8B mbarriers: 8,16,24
static constexpr int SM_BIAS    = 64;
static constexpr int SM_W1ROWS  = 576;
static constexpr int SM_TILES   = 4096;
static constexpr int TILE_BYTES = 128 * 128;
static constexpr int NSTAGE     = 3;
static constexpr int GEMM_SMEM  = SM_TILES + NSTAGE * 4 * TILE_BYTES;  // 200704

template <int MODE>
__global__ __launch_bounds__(256, 1)
void gemm_bf16s_kernel(const __nv_bfloat16* __restrict__ Ah,
                       const __nv_bfloat16* __restrict__ Al,
                       const __nv_bfloat16* __restrict__ BTh,
                       const __nv_bfloat16* __restrict__ BTl,
                       int Ktot, int Ntot,
                       const float* __restrict__ bias,
                       const int* __restrict__ action,
                       const float* __restrict__ W1,
                       float* __restrict__ outf,
                       __nv_bfloat16* __restrict__ outh,
                       __nv_bfloat16* __restrict__ outl,
                       int ob0, int nob) {
#if HAS_TCGEN05
    extern __shared__ char sm[];
    const uint32_t smb = smem_u32(sm);
    const int tid = threadIdx.x;
    const int wid = tid >> 5;
    const int lid = tid & 31;
    const int m0 = blockIdx.y * 128;
    const int n0 = blockIdx.x * 128;

    float* s_bias = (float*)(sm + SM_BIAS);
    float* s_w1   = (float*)(sm + SM_W1ROWS);

    if (wid == 0) TCGEN05_ALLOC(smb + SM_TMEMPTR, 128);
    if (tid == 0) {
#pragma unroll
        for (int s = 0; s < NSTAGE; ++s) MBARRIER_INIT(smb + SM_MBAR + s * 8, 1);
    }
    if (tid < 128) s_bias[tid] = bias[n0 + tid];
    if (MODE == 1) {
        for (int idx = tid; idx < 512; idx += 256)
            s_w1[idx] = W1[(size_t)(256 + (idx >> 7)) * HID + n0 + (idx & 127)];
    }
    __syncthreads();
    uint32_t tmem;
    asm volatile("ld.shared.b32 %0, [%1];" : "=r"(tmem) : "r"(smb + SM_TMEMPTR));

    const __nv_bfloat16* srcs[4] = {Ah, Al, BTh, BTl};
    const int row0s[4] = {m0, m0, n0, n0};
    const int NC = Ktot >> 6;  // 64-K chunks

    // issue one stage's cp.async loads (4 tiles of [128 rows x 128B], SW128)
    auto load_stage = [&](int chunk, int slot) {
        const int kt = chunk << 6;
#pragma unroll
        for (int t = 0; t < 4; ++t) {
            uint32_t st = smb + SM_TILES + (uint32_t)(slot * 4 + t) * TILE_BYTES;
            const __nv_bfloat16* g = srcs[t];
            const int r0 = row0s[t];
#pragma unroll
            for (int ii = 0; ii < 4; ++ii) {
                int idx = tid + ii * 256;       // 0..1023
                int r = idx >> 3, q = idx & 7;
                CP_ASYNC16(st + sw128(r * 128 + q * 16),
                           g + (size_t)(r0 + r) * Ktot + kt + q * 8);
            }
        }
    };

    int commits[NSTAGE] = {0, 0, 0};

    // prologue: stages 0,1
    load_stage(0, 0); CP_COMMIT();
    if (NC > 1) { load_stage(1, 1); }
    CP_COMMIT();   // commit even if empty to keep group accounting uniform

    for (int i = 0; i < NC; ++i) {
        const int slot = i % NSTAGE;
        CP_WAIT1();                 // stage i arrived (<=1 group pending)
        FENCE_ASYNC_SHARED();
        __syncthreads();
        if (wid == 0 && elect_one()) {
            uint32_t base = smb + SM_TILES + (uint32_t)(slot * 4) * TILE_BYTES;
            uint64_t dAh = make_desc(base);
            uint64_t dAl = make_desc(base + TILE_BYTES);
            uint64_t dBh = make_desc(base + 2 * TILE_BYTES);
            uint64_t dBl = make_desc(base + 3 * TILE_BYTES);
#pragma unroll
            for (int ks = 0; ks < 4; ++ks) {
                mma_bf16_ss(tmem, dAh + ks * 2, dBh + ks * 2, IDESC_128x128,
                            (i > 0 || ks > 0) ? 1u : 0u);
                mma_bf16_ss(tmem, dAh + ks * 2, dBl + ks * 2, IDESC_128x128, 1u);
                mma_bf16_ss(tmem, dAl + ks * 2, dBh + ks * 2, IDESC_128x128, 1u);
            }
            TCGEN05_COMMIT(smb + SM_MBAR + slot * 8);
        }
        commits[slot]++;
        // issue loads for chunk i+2 (slot reuse guarded by that slot's MMA)
        const int nxt = i + 2;
        if (nxt < NC) {
            const int ns = nxt % NSTAGE;
            if (commits[ns] > 0)
                MBARRIER_WAIT_PARITY(smb + SM_MBAR + ns * 8, (commits[ns] - 1) & 1);
            load_stage(nxt, ns);
        }
        CP_COMMIT();  // uniform group accounting (possibly empty)
    }
    // drain: wait latest commit of every slot
#pragma unroll
    for (int s = 0; s < NSTAGE; ++s)
        if (commits[s] > 0)
            MBARRIER_WAIT_PARITY(smb + SM_MBAR + s * 8, (commits[s] - 1) & 1);
    TCGEN05_FENCE_AFTER();

    // ------------------------- epilogue -------------------------
    const int wq = wid & 3, wc = wid >> 2;
    const int m = m0 + wq * 32 + lid;
    int jrow = 0;
    if (MODE == 1) jrow = (action[m] & 3) * 128;

#pragma unroll
    for (int cc = 0; cc < 2; ++cc) {
        const int cb = wc * 64 + cc * 32;
        uint32_t d[32];
        TCGEN05_LD_X32(d, tmem + cb);
        TCGEN05_WAIT_LD();
        float vals[32];
#pragma unroll
        for (int c = 0; c < 32; ++c)
            vals[c] = __uint_as_float(d[c]) + s_bias[cb + c];

        if (MODE == 1) {
            uint32_t ph[16], pl[16];
#pragma unroll
            for (int c = 0; c < 32; c += 2) {
                float v0 = fmaxf(vals[c] + 0.0625f * s_w1[jrow + cb + c], 0.f);
                float v1 = fmaxf(vals[c + 1] + 0.0625f * s_w1[jrow + cb + c + 1], 0.f);
                __nv_bfloat16 h0, l0, h1x, l1; split_bf16(v0, h0, l0); split_bf16(v1, h1x, l1);
                __nv_bfloat162 hp(h0, h1x), lp(l0, l1);
                ph[c >> 1] = *(uint32_t*)&hp;
                pl[c >> 1] = *(uint32_t*)&lp;
            }
            size_t o = (size_t)m * Ntot + n0 + cb;
#pragma unroll
            for (int q = 0; q < 4; ++q) {
                *(uint4*)(outh + o + q * 8) = *(uint4*)&ph[q * 4];
                *(uint4*)(outl + o + q * 8) = *(uint4*)&pl[q * 4];
            }
        } else if (MODE == 2) {
            size_t o = (size_t)m * Ntot + n0 + cb;
#pragma unroll
            for (int q = 0; q < 8; ++q)
                *(float4*)(outf + o + q * 4) = *(float4*)&vals[q * 4];
        } else {
            size_t base = (size_t)m * (OBJ * OBS) + (size_t)ob0 * OBS + n0 + cb;
            for (int ob = 0; ob < nob; ++ob) {
#pragma unroll
                for (int q = 0; q < 8; ++q)
                    *(float4*)(outf + base + (size_t)ob * OBS + q * 4) = *(float4*)&vals[q * 4];
            }
        }
    }

    __syncthreads();
    if (wid == 0) {
        TCGEN05_RELINQ();
        TCGEN05_DEALLOC(tmem, 128);
    }
#else
    // Fallback for the non-sm_103a PTX pass (never selected on GB300).
    const int tid = threadIdx.x;
    const int m0 = blockIdx.y * 128;
    const int n0 = blockIdx.x * 128;
    for (int e = tid; e < 128 * 128; e += 256) {
        int r = e >> 7, c = e & 127;
        int m = m0 + r, n = n0 + c;
        float acc = 0.f;
        for (int k = 0; k < Ktot; ++k) {
            float a = __bfloat162float(Ah[(size_t)m * Ktot + k]) +
                      __bfloat162float(Al[(size_t)m * Ktot + k]);
            float b = __bfloat162float(BTh[(size_t)n * Ktot + k]) +
                      __bfloat162float(BTl[(size_t)n * Ktot + k]);
            acc += a * b;
        }
        acc += bias[n];
        if (MODE == 1) {
            int j = action[m] & 3;
            float v = fmaxf(acc + 0.0625f * W1[(size_t)(256 + j) * HID + n], 0.f);
            __nv_bfloat16 hi, lo; split_bf16(v, hi, lo);
            outh[(size_t)m * Ntot + n] = hi;
            outl[(size_t)m * Ntot + n] = lo;
        } else if (MODE == 2) {
            outf[(size_t)m * Ntot + n] = acc;
        } else {
            size_t base = (size_t)m * (OBJ * OBS) + (size_t)ob0 * OBS + n;
            for (int ob = 0; ob < nob; ++ob) outf[base + (size_t)ob * OBS] = acc;
        }
    }
#endif
}

// ---------------------------------------------------------------------------
// LayerNorm(512) + ReLU -> bf16 hi/lo
// ---------------------------------------------------------------------------
__device__ __forceinline__ float warp_sum(float v) {
#pragma unroll
    for (int o = 16; o > 0; o >>= 1) v += __shfl_xor_sync(0xffffffffu, v, o);
    return v;
}

__global__ void ln_relu_kernel(const float* __restrict__ g,
                               const float* __restrict__ b) {
    int row = blockIdx.x;
    int t = threadIdx.x;  // 128
    const float* x = g_z2 + (size_t)row * HID;
    float4 v = ((const float4*)x)[t];
    float s  = v.x + v.y + v.z + v.w;
    float ss = v.x * v.x + v.y * v.y + v.z * v.z + v.w * v.w;
    __shared__ float red[2][4];
    float sw = warp_sum(s), ssw = warp_sum(ss);
    int wid = t >> 5, lid = t & 31;
    if (lid == 0) { red[0][wid] = sw; red[1][wid] = ssw; }
    __syncthreads();
    float ts  = red[0][0] + red[0][1] + red[0][2] + red[0][3];
    float tss = red[1][0] + red[1][1] + red[1][2] + red[1][3];
    const float invn = 1.0f / HID;
    float mu = ts * invn;
    float var = tss * invn - mu * mu;
    float rs = rsqrtf(var + 1e-5f);
    float4 gv = ((const float4*)g)[t];
    float4 bv = ((const float4*)b)[t];
    float vals[4];
    vals[0] = fmaxf((v.x - mu) * rs * gv.x + bv.x, 0.f);
    vals[1] = fmaxf((v.y - mu) * rs * gv.y + bv.y, 0.f);
    vals[2] = fmaxf((v.z - mu) * rs * gv.z + bv.z, 0.f);
    vals[3] = fmaxf((v.w - mu) * rs * gv.w + bv.w, 0.f);
    size_t base = (size_t)row * HID + t * 4;
    __nv_bfloat16 h0, l0, h1, l1;
    split_bf16(vals[0], h0, l0); split_bf16(vals[1], h1, l1);
    *(__nv_bfloat162*)(g_h2_h + base) = __nv_bfloat162(h0, h1);
    *(__nv_bfloat162*)(g_h2_l + base) = __nv_bfloat162(l0, l1);
    split_bf16(vals[2], h0, l0); split_bf16(vals[3], h1, l1);
    *(__nv_bfloat162*)(g_h2_h + base + 2) = __nv_bfloat162(h0, h1);
    *(__nv_bfloat162*)(g_h2_l + base + 2) = __nv_bfloat162(l0, l1);
}

// ---------------------------------------------------------------------------
extern "C" void kernel_launch(void* const* d_in, const int* in_sizes, int n_in,
                              void* d_out, int out_size) {
    const float* states = (const float*)d_in[0];
    const int*   action = (const int*)d_in[1];
    const float* W1     = (const float*)d_in[2];
    const float* b1     = (const float*)d_in[3];
    const float* W2     = (const float*)d_in[4];
    const float* b2     = (const float*)d_in[5];
    const float* W3     = (const float*)d_in[6];
    const float* b3     = (const float*)d_in[7];
    const float* ln_g   = (const float*)d_in[8];
    const float* ln_b   = (const float*)d_in[9];
    float* out = (float*)d_out;

    __nv_bfloat16 *sbh, *sbl, *h1h, *h1l, *h2h, *h2l;
    __nv_bfloat16 *w1h, *w1l, *w2h, *w2l, *w3h, *w3l;
    float* z2p;
    cudaGetSymbolAddress((void**)&sbh, g_sbar_h);
    cudaGetSymbolAddress((void**)&sbl, g_sbar_l);
    cudaGetSymbolAddress((void**)&h1h, g_h1_h);
    cudaGetSymbolAddress((void**)&h1l, g_h1_l);
    cudaGetSymbolAddress((void**)&h2h, g_h2_h);
    cudaGetSymbolAddress((void**)&h2l, g_h2_l);
    cudaGetSymbolAddress((void**)&w1h, g_W1T_h);
    cudaGetSymbolAddress((void**)&w1l, g_W1T_l);
    cudaGetSymbolAddress((void**)&w2h, g_W2T_h);
    cudaGetSymbolAddress((void**)&w2l, g_W2T_l);
    cudaGetSymbolAddress((void**)&w3h, g_W3T_h);
    cudaGetSymbolAddress((void**)&w3l, g_W3T_l);
    cudaGetSymbolAddress((void**)&z2p, g_z2);

    cudaFuncSetAttribute(gemm_bf16s_kernel<1>,
                         cudaFuncAttributeMaxDynamicSharedMemorySize, GEMM_SMEM);
    cudaFuncSetAttribute(gemm_bf16s_kernel<2>,
                         cudaFuncAttributeMaxDynamicSharedMemorySize, GEMM_SMEM);
    cudaFuncSetAttribute(gemm_bf16s_kernel<3>,
                         cudaFuncAttributeMaxDynamicSharedMemorySize, GEMM_SMEM);

    tconv_kernel<<<dim3(16, 16, 3), dim3(32, 8)>>>(W1, W2, W3);
    reduce_states_kernel<<<BATCH / 4, 256>>>(states);
    gemm_bf16s_kernel<1><<<dim3(HID / 128, BATCH / 128), 256, GEMM_SMEM>>>(
        sbh, sbl, w1h, w1l, OBS, HID, b1, action, W1, nullptr, h1h, h1l, 0, 0);
    gemm_bf16s_kernel<2><<<dim3(HID / 128, BATCH / 128), 256, GEMM_SMEM>>>(
        h1h, h1l, w2h, w2l, HID, HID, b2, nullptr, nullptr, z2p, nullptr, nullptr, 0, 0);
    ln_relu_kernel<<<BATCH, 128>>>(ln_g, ln_b);
    // GEMM3 split over objects (z=0 -> obj 0..7, z=1 -> obj 8..15): doubles
    // writer CTAs for the 64MB broadcast output, MMA recompute is cheap.
    gemm_bf16s_kernel<3><<<dim3(OBS / 128, BATCH / 128), 256, GEMM_SMEM>>>(
        h2h, h2l, w3h, w3l, HID, OBS, b3, nullptr, nullptr, out, nullptr, nullptr, 0, 8);
    gemm_bf16s_kernel<3><<<dim3(OBS / 128, BATCH / 128), 256, GEMM_SMEM>>>(
        h2h, h2l, w3h, w3l, HID, OBS, b3, nullptr, nullptr, out, nullptr, nullptr, 8, 8);
}

// round 5
// speedup vs baseline: 3.6990x; 1.4202x over previous
#include <cuda_runtime.h>
#include <cuda_bf16.h>
#include <cstdint>
#include <math.h>

#define BATCH 4096
#define OBJ   16
#define OBS   256
#define HID   512

#if defined(__CUDA_ARCH__) && (defined(__CUDA_ARCH_FEAT_SM103_ALL) || \
    (defined(__CUDA_ARCH_SPECIFIC__) && __CUDA_ARCH_SPECIFIC__ == 1030) || \
    (defined(__CUDA_ARCH_FAMILY_SPECIFIC__) && __CUDA_ARCH_FAMILY_SPECIFIC__ == 1030))
#define HAS_TCGEN05 1
#else
#define HAS_TCGEN05 0
#endif

// ---------------------------------------------------------------------------
// Scratch
// ---------------------------------------------------------------------------
__device__ __nv_bfloat16 g_sbar_h[BATCH * OBS], g_sbar_l[BATCH * OBS];
__device__ __nv_bfloat16 g_h1_h[BATCH * HID], g_h1_l[BATCH * HID];
__device__ float         g_z2[BATCH * HID];
__device__ __nv_bfloat16 g_h2_h[BATCH * HID], g_h2_l[BATCH * HID];
__device__ __nv_bfloat16 g_W1T_h[HID * OBS], g_W1T_l[HID * OBS];
__device__ __nv_bfloat16 g_W2T_h[HID * HID], g_W2T_l[HID * HID];
__device__ __nv_bfloat16 g_W3T_h[OBS * HID], g_W3T_l[OBS * HID];

// ---------------------------------------------------------------------------
// helpers
// ---------------------------------------------------------------------------
__device__ __forceinline__ uint32_t smem_u32(const void* p) {
    uint32_t a;
    asm("{ .reg .u64 t; cvta.to.shared.u64 t, %1; cvt.u32.u64 %0, t; }"
        : "=r"(a) : "l"(p));
    return a;
}
__device__ __forceinline__ uint32_t sw128(uint32_t off) {
    return off ^ ((off >> 3) & 0x70);
}
__device__ __forceinline__ void split_bf16(float v, __nv_bfloat16& hi, __nv_bfloat16& lo) {
    hi = __float2bfloat16(v);
    lo = __float2bfloat16(v - __bfloat162float(hi));
}

#define CP_ASYNC16(smem_a, gptr)                                               \
    asm volatile("cp.async.cg.shared.global [%0], [%1], 16;"                   \
                 :: "r"((uint32_t)(smem_a)), "l"(gptr) : "memory")
#define CP_MBAR_ARRIVE(mbar)                                                   \
    asm volatile("cp.async.mbarrier.arrive.noinc.shared.b64 [%0];"             \
                 :: "r"((uint32_t)(mbar)) : "memory")
#define MBARRIER_INIT(mbar, cnt)                                               \
    asm volatile("mbarrier.init.shared.b64 [%0], %1;"                          \
                 :: "r"((uint32_t)(mbar)), "r"((uint32_t)(cnt)) : "memory")
#define MBARRIER_WAIT_PARITY(mbar_a, par_a) do {                               \
    uint32_t _mb = (uint32_t)(mbar_a);                                         \
    uint32_t _pa = (uint32_t)(par_a);                                          \
    uint32_t _done;                                                            \
    asm volatile("{\n\t.reg .pred p;\n\t"                                      \
        "mbarrier.try_wait.parity.acquire.cta.shared::cta.b64 p, [%1], %2;\n\t"\
        "selp.b32 %0, 1, 0, p;\n\t}"                                           \
        : "=r"(_done) : "r"(_mb), "r"(_pa) : "memory");                        \
    if (!_done) {                                                              \
        asm volatile("{\n\t.reg .pred P1;\n\t"                                 \
            "WL_%=:\n\t"                                                       \
            "mbarrier.try_wait.parity.acquire.cta.shared::cta.b64 P1, [%0], %1, 0x989680;\n\t" \
            "@P1 bra.uni WD_%=;\n\t"                                           \
            "bra.uni WL_%=;\n\t"                                               \
            "WD_%=:\n\t}" :: "r"(_mb), "r"(_pa) : "memory");                   \
    }                                                                          \
} while (0)

#if HAS_TCGEN05
__device__ __forceinline__ uint32_t elect_one() {
    uint32_t pred;
    asm volatile("{\n\t.reg .pred p;\n\telect.sync _|p, 0xFFFFFFFF;\n\t"
                 "selp.b32 %0, 1, 0, p;\n\t}" : "=r"(pred));
    return pred;
}
#define TCGEN05_ALLOC(sm_addr, ncols)                                          \
    asm volatile("tcgen05.alloc.cta_group::1.sync.aligned.shared::cta.b32 [%0], %1;" \
                 :: "r"((uint32_t)(sm_addr)), "r"((uint32_t)(ncols)) : "memory")
#define TCGEN05_DEALLOC(tmem, ncols)                                           \
    asm volatile("tcgen05.dealloc.cta_group::1.sync.aligned.b32 %0, %1;"       \
                 :: "r"(tmem), "r"((uint32_t)(ncols)))
#define TCGEN05_RELINQ()                                                       \
    asm volatile("tcgen05.relinquish_alloc_permit.cta_group::1.sync.aligned;")
#define TCGEN05_COMMIT(mbar)                                                   \
    asm volatile("tcgen05.commit.cta_group::1.mbarrier::arrive::one.shared::cluster.b64 [%0];" \
                 :: "r"((uint32_t)(mbar)) : "memory")
#define TCGEN05_WAIT_LD() asm volatile("tcgen05.wait::ld.sync.aligned;" ::: "memory")
#define TCGEN05_FENCE_AFTER() asm volatile("tcgen05.fence::after_thread_sync;" ::: "memory")
#define FENCE_ASYNC_SHARED() asm volatile("fence.proxy.async.shared::cta;" ::: "memory")

#define TCGEN05_LD_X32(r, tmem_addr)                                           \
    asm volatile("tcgen05.ld.sync.aligned.32x32b.x32.b32 "                     \
        "{%0, %1, %2, %3, %4, %5, %6, %7, "                                    \
        " %8, %9, %10, %11, %12, %13, %14, %15, "                              \
        " %16, %17, %18, %19, %20, %21, %22, %23, "                            \
        " %24, %25, %26, %27, %28, %29, %30, %31}, [%32];"                     \
        : "=r"((r)[0]),  "=r"((r)[1]),  "=r"((r)[2]),  "=r"((r)[3]),           \
          "=r"((r)[4]),  "=r"((r)[5]),  "=r"((r)[6]),  "=r"((r)[7]),           \
          "=r"((r)[8]),  "=r"((r)[9]),  "=r"((r)[10]), "=r"((r)[11]),          \
          "=r"((r)[12]), "=r"((r)[13]), "=r"((r)[14]), "=r"((r)[15]),          \
          "=r"((r)[16]), "=r"((r)[17]), "=r"((r)[18]), "=r"((r)[19]),          \
          "=r"((r)[20]), "=r"((r)[21]), "=r"((r)[22]), "=r"((r)[23]),          \
          "=r"((r)[24]), "=r"((r)[25]), "=r"((r)[26]), "=r"((r)[27]),          \
          "=r"((r)[28]), "=r"((r)[29]), "=r"((r)[30]), "=r"((r)[31])           \
        : "r"(tmem_addr))

__device__ __forceinline__ void mma_bf16_ss(uint32_t d, uint64_t a, uint64_t b,
                                            uint32_t idesc, uint32_t en) {
    asm volatile(
        "{\n\t.reg .pred p;\n\tsetp.ne.u32 p, %4, 0;\n\t"
        "tcgen05.mma.cta_group::1.kind::f16 [%0], %1, %2, %3, {%5, %5, %5, %5}, p;\n\t}"
        :: "r"(d), "l"(a), "l"(b), "r"(idesc), "r"(en), "r"(0u) : "memory");
}
__device__ __forceinline__ uint64_t make_desc(uint32_t addr) {
    return ((uint64_t)2 << 61) | ((uint64_t)1 << 46) | ((uint64_t)64 << 32) |
           ((uint64_t)1 << 16) | ((uint64_t)(addr >> 4) & 0x3FFF);
}
static constexpr uint32_t IDESC_128x128 = 0x8200490u;
#endif  // HAS_TCGEN05

// ---------------------------------------------------------------------------
// Fused prep kernel: blocks [0,1024) do the per-batch object mean (-> bf16
// hi/lo); blocks [1024,1792) transpose + split the weight matrices.
// ---------------------------------------------------------------------------
__global__ void prep_kernel(const float* __restrict__ states,
                            const float* __restrict__ W1,
                            const float* __restrict__ W2,
                            const float* __restrict__ W3) {
    if (blockIdx.x < 1024) {
        int lb = threadIdx.x >> 6;
        int d4 = threadIdx.x & 63;
        int b  = blockIdx.x * 4 + lb;
        const float4* src = (const float4*)(states + (size_t)b * OBJ * OBS);
        float4 acc = make_float4(0.f, 0.f, 0.f, 0.f);
#pragma unroll
        for (int o = 0; o < OBJ; ++o) {
            float4 v = src[o * (OBS / 4) + d4];
            acc.x += v.x; acc.y += v.y; acc.z += v.z; acc.w += v.w;
        }
        const float inv = 1.0f / OBJ;
        float vals[4] = {acc.x * inv, acc.y * inv, acc.z * inv, acc.w * inv};
        size_t base = (size_t)b * OBS + d4 * 4;
#pragma unroll
        for (int c = 0; c < 4; ++c) {
            __nv_bfloat16 hi, lo; split_bf16(vals[c], hi, lo);
            g_sbar_h[base + c] = hi; g_sbar_l[base + c] = lo;
        }
    } else {
        int r = blockIdx.x - 1024;       // 0..767
        int bz = r >> 8;                 // matrix id
        int rem = r & 255;               // 16x16 tile grid
        int bx = rem & 15, by = rem >> 4;
        const float* W; __nv_bfloat16 *Th, *Tl; int K, N;
        if (bz == 0)      { W = W1; Th = g_W1T_h; Tl = g_W1T_l; K = OBS; N = HID; }
        else if (bz == 1) { W = W2; Th = g_W2T_h; Tl = g_W2T_l; K = HID; N = HID; }
        else              { W = W3; Th = g_W3T_h; Tl = g_W3T_l; K = HID; N = OBS; }
        int k0 = by * 32, n0 = bx * 32;
        if (k0 >= K || n0 >= N) return;
        __shared__ float t[32][33];
        int tx = threadIdx.x & 31, ty = threadIdx.x >> 5;  // 32x8
#pragma unroll
        for (int i = 0; i < 4; ++i)
            t[ty + i * 8][tx] = W[(size_t)(k0 + ty + i * 8) * N + n0 + tx];
        __syncthreads();
#pragma unroll
        for (int i = 0; i < 4; ++i) {
            int n = ty + i * 8;
            float v = t[tx][n];
            __nv_bfloat16 hi, lo; split_bf16(v, hi, lo);
            size_t o = (size_t)(n0 + n) * K + k0 + tx;
            Th[o] = hi; Tl[o] = lo;
        }
    }
}

// ---------------------------------------------------------------------------
// tcgen05 bf16-split GEMM, producer/consumer mbarrier pipeline, 3 slots.
// MODE 1: h1 = relu(D + b1 + W1row/16) -> bf16 hi/lo
// MODE 2: z2 = D + b2 -> fp32
// MODE 3: out[(m*16 + blockIdx.z*nob + j)*256 + n] = D + b3, j = 0..nob-1
// ---------------------------------------------------------------------------
static constexpr int SM_TMEMPTR = 0;
static constexpr int SM_FULL    = 16;    // 3 x 8B
static constexpr int SM_EMPTY   = 40;    // 3 x 8B
static constexpr int SM_BIAS    = 64;
static constexpr int SM_W1ROWS  = 576;
static constexpr int SM_TILES   = 4096;
static constexpr int TILE_BYTES = 128 * 128;
static constexpr int NSLOT      = 3;
static constexpr int GEMM_SMEM  = SM_TILES + NSLOT * 4 * TILE_BYTES;  // 200704

template <int MODE>
__global__ __launch_bounds__(256, 1)
void gemm_bf16s_kernel(const __nv_bfloat16* __restrict__ Ah,
                       const __nv_bfloat16* __restrict__ Al,
                       const __nv_bfloat16* __restrict__ BTh,
                       const __nv_bfloat16* __restrict__ BTl,
                       int Ktot, int Ntot,
                       const float* __restrict__ bias,
                       const int* __restrict__ action,
                       const float* __restrict__ W1,
                       float* __restrict__ outf,
                       __nv_bfloat16* __restrict__ outh,
                       __nv_bfloat16* __restrict__ outl,
                       int nob) {
#if HAS_TCGEN05
    extern __shared__ char sm[];
    const uint32_t smb = smem_u32(sm);
    const int tid = threadIdx.x;
    const int wid = tid >> 5;
    const int lid = tid & 31;
    const int m0 = blockIdx.y * 128;
    const int n0 = blockIdx.x * 128;

    float* s_bias = (float*)(sm + SM_BIAS);
    float* s_w1   = (float*)(sm + SM_W1ROWS);

    if (wid == 0) TCGEN05_ALLOC(smb + SM_TMEMPTR, 128);
    if (tid == 0) {
#pragma unroll
        for (int s = 0; s < NSLOT; ++s) {
            MBARRIER_INIT(smb + SM_FULL + s * 8, 256);
            MBARRIER_INIT(smb + SM_EMPTY + s * 8, 1);
        }
    }
    if (tid < 128) s_bias[tid] = bias[n0 + tid];
    if (MODE == 1) {
        for (int idx = tid; idx < 512; idx += 256)
            s_w1[idx] = W1[(size_t)(256 + (idx >> 7)) * HID + n0 + (idx & 127)];
    }
    __syncthreads();
    uint32_t tmem;
    asm volatile("ld.shared.b32 %0, [%1];" : "=r"(tmem) : "r"(smb + SM_TMEMPTR));

    const __nv_bfloat16* srcs[4] = {Ah, Al, BTh, BTl};
    const int row0s[4] = {m0, m0, n0, n0};
    const int NC = Ktot >> 6;  // 64-K chunks

    // per-thread cp.async of one stage (16 x 16B) + completion arrive
    auto load_stage = [&](int chunk, int slot) {
        const int kt = chunk << 6;
#pragma unroll
        for (int t = 0; t < 4; ++t) {
            uint32_t st = smb + SM_TILES + (uint32_t)(slot * 4 + t) * TILE_BYTES;
            const __nv_bfloat16* g = srcs[t];
            const int r0 = row0s[t];
#pragma unroll
            for (int ii = 0; ii < 4; ++ii) {
                int idx = tid + ii * 256;       // 0..1023
                int r = idx >> 3, q = idx & 7;
                CP_ASYNC16(st + sw128(r * 128 + q * 16),
                           g + (size_t)(r0 + r) * Ktot + kt + q * 8);
            }
        }
        CP_MBAR_ARRIVE(smb + SM_FULL + slot * 8);
    };

    // prologue: fill all 3 slots (NC >= 4 in all uses)
#pragma unroll
    for (int c = 0; c < NSLOT; ++c) load_stage(c, c);

    const bool consumer = (wid == 0) && elect_one();
    for (int c = 0; c < NC; ++c) {
        const int s = c % NSLOT;
        const int k = c / NSLOT;
        if (consumer) {
            MBARRIER_WAIT_PARITY(smb + SM_FULL + s * 8, k & 1);
            FENCE_ASYNC_SHARED();
            uint32_t base = smb + SM_TILES + (uint32_t)(s * 4) * TILE_BYTES;
            uint64_t dAh = make_desc(base);
            uint64_t dAl = make_desc(base + TILE_BYTES);
            uint64_t dBh = make_desc(base + 2 * TILE_BYTES);
            uint64_t dBl = make_desc(base + 3 * TILE_BYTES);
#pragma unroll
            for (int ks = 0; ks < 4; ++ks) {
                mma_bf16_ss(tmem, dAh + ks * 2, dBh + ks * 2, IDESC_128x128,
                            (c > 0 || ks > 0) ? 1u : 0u);
                mma_bf16_ss(tmem, dAh + ks * 2, dBl + ks * 2, IDESC_128x128, 1u);
                mma_bf16_ss(tmem, dAl + ks * 2, dBh + ks * 2, IDESC_128x128, 1u);
            }
            TCGEN05_COMMIT(smb + SM_EMPTY + s * 8);
        }
        // producers: refill this slot for chunk c+3 once its MMAs drained
        if (c + NSLOT < NC) {
            MBARRIER_WAIT_PARITY(smb + SM_EMPTY + s * 8, k & 1);
            load_stage(c + NSLOT, s);
        }
    }
    // all MMAs done == last commit completed
    {
        const int cl = NC - 1;
        MBARRIER_WAIT_PARITY(smb + SM_EMPTY + (cl % NSLOT) * 8, (cl / NSLOT) & 1);
    }
    TCGEN05_FENCE_AFTER();

    // ------------------------- epilogue -------------------------
    const int wq = wid & 3, wc = wid >> 2;
    const int m = m0 + wq * 32 + lid;
    int jrow = 0;
    if (MODE == 1) jrow = (action[m] & 3) * 128;

#pragma unroll
    for (int cc = 0; cc < 2; ++cc) {
        const int cb = wc * 64 + cc * 32;
        uint32_t d[32];
        TCGEN05_LD_X32(d, tmem + cb);
        TCGEN05_WAIT_LD();
        float vals[32];
#pragma unroll
        for (int c = 0; c < 32; ++c)
            vals[c] = __uint_as_float(d[c]) + s_bias[cb + c];

        if (MODE == 1) {
            uint32_t ph[16], pl[16];
#pragma unroll
            for (int c = 0; c < 32; c += 2) {
                float v0 = fmaxf(vals[c] + 0.0625f * s_w1[jrow + cb + c], 0.f);
                float v1 = fmaxf(vals[c + 1] + 0.0625f * s_w1[jrow + cb + c + 1], 0.f);
                __nv_bfloat16 h0, l0, h1x, l1; split_bf16(v0, h0, l0); split_bf16(v1, h1x, l1);
                __nv_bfloat162 hp(h0, h1x), lp(l0, l1);
                ph[c >> 1] = *(uint32_t*)&hp;
                pl[c >> 1] = *(uint32_t*)&lp;
            }
            size_t o = (size_t)m * Ntot + n0 + cb;
#pragma unroll
            for (int q = 0; q < 4; ++q) {
                *(uint4*)(outh + o + q * 8) = *(uint4*)&ph[q * 4];
                *(uint4*)(outl + o + q * 8) = *(uint4*)&pl[q * 4];
            }
        } else if (MODE == 2) {
            size_t o = (size_t)m * Ntot + n0 + cb;
#pragma unroll
            for (int q = 0; q < 8; ++q)
                *(float4*)(outf + o + q * 4) = *(float4*)&vals[q * 4];
        } else {
            size_t base = (size_t)m * (OBJ * OBS) +
                          (size_t)(blockIdx.z * nob) * OBS + n0 + cb;
            for (int ob = 0; ob < nob; ++ob) {
#pragma unroll
                for (int q = 0; q < 8; ++q)
                    *(float4*)(outf + base + (size_t)ob * OBS + q * 4) = *(float4*)&vals[q * 4];
            }
        }
    }

    __syncthreads();
    if (wid == 0) {
        TCGEN05_RELINQ();
        TCGEN05_DEALLOC(tmem, 128);
    }
#else
    // Fallback for the non-sm_103a PTX pass (never selected on GB300).
    const int tid = threadIdx.x;
    const int m0 = blockIdx.y * 128;
    const int n0 = blockIdx.x * 128;
    for (int e = tid; e < 128 * 128; e += 256) {
        int r = e >> 7, c = e & 127;
        int m = m0 + r, n = n0 + c;
        float acc = 0.f;
        for (int k = 0; k < Ktot; ++k) {
            float a = __bfloat162float(Ah[(size_t)m * Ktot + k]) +
                      __bfloat162float(Al[(size_t)m * Ktot + k]);
            float b = __bfloat162float(BTh[(size_t)n * Ktot + k]) +
                      __bfloat162float(BTl[(size_t)n * Ktot + k]);
            acc += a * b;
        }
        acc += bias[n];
        if (MODE == 1) {
            int j = action[m] & 3;
            float v = fmaxf(acc + 0.0625f * W1[(size_t)(256 + j) * HID + n], 0.f);
            __nv_bfloat16 hi, lo; split_bf16(v, hi, lo);
            outh[(size_t)m * Ntot + n] = hi;
            outl[(size_t)m * Ntot + n] = lo;
        } else if (MODE == 2) {
            outf[(size_t)m * Ntot + n] = acc;
        } else {
            size_t base = (size_t)m * (OBJ * OBS) + (size_t)(blockIdx.z * nob) * OBS + n;
            for (int ob = 0; ob < nob; ++ob) outf[base + (size_t)ob * OBS] = acc;
        }
    }
#endif
}

// ---------------------------------------------------------------------------
// LayerNorm(512) + ReLU -> bf16 hi/lo
// ---------------------------------------------------------------------------
__device__ __forceinline__ float warp_sum(float v) {
#pragma unroll
    for (int o = 16; o > 0; o >>= 1) v += __shfl_xor_sync(0xffffffffu, v, o);
    return v;
}

__global__ void ln_relu_kernel(const float* __restrict__ g,
                               const float* __restrict__ b) {
    int row = blockIdx.x;
    int t = threadIdx.x;  // 128
    const float* x = g_z2 + (size_t)row * HID;
    float4 v = ((const float4*)x)[t];
    float s  = v.x + v.y + v.z + v.w;
    float ss = v.x * v.x + v.y * v.y + v.z * v.z + v.w * v.w;
    __shared__ float red[2][4];
    float sw = warp_sum(s), ssw = warp_sum(ss);
    int wid = t >> 5, lid = t & 31;
    if (lid == 0) { red[0][wid] = sw; red[1][wid] = ssw; }
    __syncthreads();
    float ts  = red[0][0] + red[0][1] + red[0][2] + red[0][3];
    float tss = red[1][0] + red[1][1] + red[1][2] + red[1][3];
    const float invn = 1.0f / HID;
    float mu = ts * invn;
    float var = tss * invn - mu * mu;
    float rs = rsqrtf(var + 1e-5f);
    float4 gv = ((const float4*)g)[t];
    float4 bv = ((const float4*)b)[t];
    float vals[4];
    vals[0] = fmaxf((v.x - mu) * rs * gv.x + bv.x, 0.f);
    vals[1] = fmaxf((v.y - mu) * rs * gv.y + bv.y, 0.f);
    vals[2] = fmaxf((v.z - mu) * rs * gv.z + bv.z, 0.f);
    vals[3] = fmaxf((v.w - mu) * rs * gv.w + bv.w, 0.f);
    size_t base = (size_t)row * HID + t * 4;
    __nv_bfloat16 h0, l0, h1, l1;
    split_bf16(vals[0], h0, l0); split_bf16(vals[1], h1, l1);
    *(__nv_bfloat162*)(g_h2_h + base) = __nv_bfloat162(h0, h1);
    *(__nv_bfloat162*)(g_h2_l + base) = __nv_bfloat162(l0, l1);
    split_bf16(vals[2], h0, l0); split_bf16(vals[3], h1, l1);
    *(__nv_bfloat162*)(g_h2_h + base + 2) = __nv_bfloat162(h0, h1);
    *(__nv_bfloat162*)(g_h2_l + base + 2) = __nv_bfloat162(l0, l1);
}

// ---------------------------------------------------------------------------
extern "C" void kernel_launch(void* const* d_in, const int* in_sizes, int n_in,
                              void* d_out, int out_size) {
    const float* states = (const float*)d_in[0];
    const int*   action = (const int*)d_in[1];
    const float* W1     = (const float*)d_in[2];
    const float* b1     = (const float*)d_in[3];
    const float* W2     = (const float*)d_in[4];
    const float* b2     = (const float*)d_in[5];
    const float* W3     = (const float*)d_in[6];
    const float* b3     = (const float*)d_in[7];
    const float* ln_g   = (const float*)d_in[8];
    const float* ln_b   = (const float*)d_in[9];
    float* out = (float*)d_out;

    __nv_bfloat16 *sbh, *sbl, *h1h, *h1l, *h2h, *h2l;
    __nv_bfloat16 *w1h, *w1l, *w2h, *w2l, *w3h, *w3l;
    float* z2p;
    cudaGetSymbolAddress((void**)&sbh, g_sbar_h);
    cudaGetSymbolAddress((void**)&sbl, g_sbar_l);
    cudaGetSymbolAddress((void**)&h1h, g_h1_h);
    cudaGetSymbolAddress((void**)&h1l, g_h1_l);
    cudaGetSymbolAddress((void**)&h2h, g_h2_h);
    cudaGetSymbolAddress((void**)&h2l, g_h2_l);
    cudaGetSymbolAddress((void**)&w1h, g_W1T_h);
    cudaGetSymbolAddress((void**)&w1l, g_W1T_l);
    cudaGetSymbolAddress((void**)&w2h, g_W2T_h);
    cudaGetSymbolAddress((void**)&w2l, g_W2T_l);
    cudaGetSymbolAddress((void**)&w3h, g_W3T_h);
    cudaGetSymbolAddress((void**)&w3l, g_W3T_l);
    cudaGetSymbolAddress((void**)&z2p, g_z2);

    cudaFuncSetAttribute(gemm_bf16s_kernel<1>,
                         cudaFuncAttributeMaxDynamicSharedMemorySize, GEMM_SMEM);
    cudaFuncSetAttribute(gemm_bf16s_kernel<2>,
                         cudaFuncAttributeMaxDynamicSharedMemorySize, GEMM_SMEM);
    cudaFuncSetAttribute(gemm_bf16s_kernel<3>,
                         cudaFuncAttributeMaxDynamicSharedMemorySize, GEMM_SMEM);

    // 0) fused: object-mean (blocks 0..1023) + weight transpose/split (1024..1791)
    prep_kernel<<<1792, 256>>>(states, W1, W2, W3);
    // 1) h1 = relu(sbar @ W1[:256] + b1 + W1[256+a%4]/16) -> bf16 hi/lo
    gemm_bf16s_kernel<1><<<dim3(HID / 128, BATCH / 128), 256, GEMM_SMEM>>>(
        sbh, sbl, w1h, w1l, OBS, HID, b1, action, W1, nullptr, h1h, h1l, 0);
    // 2) z2 = h1 @ W2 + b2 -> fp32
    gemm_bf16s_kernel<2><<<dim3(HID / 128, BATCH / 128), 256, GEMM_SMEM>>>(
        h1h, h1l, w2h, w2l, HID, HID, b2, nullptr, nullptr, z2p, nullptr, nullptr, 0);
    // 3) h2 = relu(LN(z2)) -> bf16 hi/lo
    ln_relu_kernel<<<BATCH, 128>>>(ln_g, ln_b);
    // 4) out = broadcast_obj(h2 @ W3 + b3), object dim split across grid.z
    gemm_bf16s_kernel<3><<<dim3(OBS / 128, BATCH / 128, 2), 256, GEMM_SMEM>>>(
        h2h, h2l, w3h, w3l, HID, OBS, b3, nullptr, nullptr, out, nullptr, nullptr, 8);
}

// round 6
// speedup vs baseline: 4.6171x; 1.2482x over previous
#include <cuda_runtime.h>
#include <cuda_bf16.h>
#include <cstdint>
#include <math.h>

#define BATCH 4096
#define OBJ   16
#define OBS   256
#define HID   512

#if defined(__CUDA_ARCH__) && (defined(__CUDA_ARCH_FEAT_SM103_ALL) || \
    (defined(__CUDA_ARCH_SPECIFIC__) && __CUDA_ARCH_SPECIFIC__ == 1030) || \
    (defined(__CUDA_ARCH_FAMILY_SPECIFIC__) && __CUDA_ARCH_FAMILY_SPECIFIC__ == 1030))
#define HAS_TCGEN05 1
#else
#define HAS_TCGEN05 0
#endif

// ---------------------------------------------------------------------------
// Scratch
// ---------------------------------------------------------------------------
__device__ __nv_bfloat16 g_sbar_h[BATCH * OBS], g_sbar_l[BATCH * OBS];
__device__ __nv_bfloat16 g_h1_h[BATCH * HID], g_h1_l[BATCH * HID];
__device__ float         g_z2[BATCH * HID];
__device__ __nv_bfloat16 g_h2_h[BATCH * HID], g_h2_l[BATCH * HID];
__device__ __nv_bfloat16 g_W1T_h[HID * OBS], g_W1T_l[HID * OBS];
__device__ __nv_bfloat16 g_W2T_h[HID * HID], g_W2T_l[HID * HID];
__device__ __nv_bfloat16 g_W3T_h[OBS * HID], g_W3T_l[OBS * HID];

// ---------------------------------------------------------------------------
// helpers
// ---------------------------------------------------------------------------
__device__ __forceinline__ uint32_t smem_u32(const void* p) {
    uint32_t a;
    asm("{ .reg .u64 t; cvta.to.shared.u64 t, %1; cvt.u32.u64 %0, t; }"
        : "=r"(a) : "l"(p));
    return a;
}
__device__ __forceinline__ uint32_t sw128(uint32_t off) {
    return off ^ ((off >> 3) & 0x70);
}
__device__ __forceinline__ void split_bf16(float v, __nv_bfloat16& hi, __nv_bfloat16& lo) {
    hi = __float2bfloat16(v);
    lo = __float2bfloat16(v - __bfloat162float(hi));
}

#define CP_ASYNC16(smem_a, gptr)                                               \
    asm volatile("cp.async.cg.shared.global [%0], [%1], 16;"                   \
                 :: "r"((uint32_t)(smem_a)), "l"(gptr) : "memory")
#define CP_MBAR_ARRIVE(mbar)                                                   \
    asm volatile("cp.async.mbarrier.arrive.noinc.shared.b64 [%0];"             \
                 :: "r"((uint32_t)(mbar)) : "memory")
#define MBARRIER_INIT(mbar, cnt)                                               \
    asm volatile("mbarrier.init.shared.b64 [%0], %1;"                          \
                 :: "r"((uint32_t)(mbar)), "r"((uint32_t)(cnt)) : "memory")
#define MBARRIER_WAIT_PARITY(mbar_a, par_a) do {                               \
    uint32_t _mb = (uint32_t)(mbar_a);                                         \
    uint32_t _pa = (uint32_t)(par_a);                                          \
    uint32_t _done;                                                            \
    asm volatile("{\n\t.reg .pred p;\n\t"                                      \
        "mbarrier.try_wait.parity.acquire.cta.shared::cta.b64 p, [%1], %2;\n\t"\
        "selp.b32 %0, 1, 0, p;\n\t}"                                           \
        : "=r"(_done) : "r"(_mb), "r"(_pa) : "memory");                        \
    if (!_done) {                                                              \
        asm volatile("{\n\t.reg .pred P1;\n\t"                                 \
            "WL_%=:\n\t"                                                       \
            "mbarrier.try_wait.parity.acquire.cta.shared::cta.b64 P1, [%0], %1, 0x989680;\n\t" \
            "@P1 bra.uni WD_%=;\n\t"                                           \
            "bra.uni WL_%=;\n\t"                                               \
            "WD_%=:\n\t}" :: "r"(_mb), "r"(_pa) : "memory");                   \
    }                                                                          \
} while (0)

#if HAS_TCGEN05
__device__ __forceinline__ uint32_t elect_one() {
    uint32_t pred;
    asm volatile("{\n\t.reg .pred p;\n\telect.sync _|p, 0xFFFFFFFF;\n\t"
                 "selp.b32 %0, 1, 0, p;\n\t}" : "=r"(pred));
    return pred;
}
#define TCGEN05_ALLOC(sm_addr, ncols)                                          \
    asm volatile("tcgen05.alloc.cta_group::1.sync.aligned.shared::cta.b32 [%0], %1;" \
                 :: "r"((uint32_t)(sm_addr)), "r"((uint32_t)(ncols)) : "memory")
#define TCGEN05_DEALLOC(tmem, ncols)                                           \
    asm volatile("tcgen05.dealloc.cta_group::1.sync.aligned.b32 %0, %1;"       \
                 :: "r"(tmem), "r"((uint32_t)(ncols)))
#define TCGEN05_RELINQ()                                                       \
    asm volatile("tcgen05.relinquish_alloc_permit.cta_group::1.sync.aligned;")
#define TCGEN05_COMMIT(mbar)                                                   \
    asm volatile("tcgen05.commit.cta_group::1.mbarrier::arrive::one.shared::cluster.b64 [%0];" \
                 :: "r"((uint32_t)(mbar)) : "memory")
#define TCGEN05_WAIT_LD() asm volatile("tcgen05.wait::ld.sync.aligned;" ::: "memory")
#define TCGEN05_FENCE_AFTER() asm volatile("tcgen05.fence::after_thread_sync;" ::: "memory")
#define FENCE_ASYNC_SHARED() asm volatile("fence.proxy.async.shared::cta;" ::: "memory")

#define TCGEN05_LD_X32(r, tmem_addr)                                           \
    asm volatile("tcgen05.ld.sync.aligned.32x32b.x32.b32 "                     \
        "{%0, %1, %2, %3, %4, %5, %6, %7, "                                    \
        " %8, %9, %10, %11, %12, %13, %14, %15, "                              \
        " %16, %17, %18, %19, %20, %21, %22, %23, "                            \
        " %24, %25, %26, %27, %28, %29, %30, %31}, [%32];"                     \
        : "=r"((r)[0]),  "=r"((r)[1]),  "=r"((r)[2]),  "=r"((r)[3]),           \
          "=r"((r)[4]),  "=r"((r)[5]),  "=r"((r)[6]),  "=r"((r)[7]),           \
          "=r"((r)[8]),  "=r"((r)[9]),  "=r"((r)[10]), "=r"((r)[11]),          \
          "=r"((r)[12]), "=r"((r)[13]), "=r"((r)[14]), "=r"((r)[15]),          \
          "=r"((r)[16]), "=r"((r)[17]), "=r"((r)[18]), "=r"((r)[19]),          \
          "=r"((r)[20]), "=r"((r)[21]), "=r"((r)[22]), "=r"((r)[23]),          \
          "=r"((r)[24]), "=r"((r)[25]), "=r"((r)[26]), "=r"((r)[27]),          \
          "=r"((r)[28]), "=r"((r)[29]), "=r"((r)[30]), "=r"((r)[31])           \
        : "r"(tmem_addr))

__device__ __forceinline__ void mma_bf16_ss(uint32_t d, uint64_t a, uint64_t b,
                                            uint32_t idesc, uint32_t en) {
    asm volatile(
        "{\n\t.reg .pred p;\n\tsetp.ne.u32 p, %4, 0;\n\t"
        "tcgen05.mma.cta_group::1.kind::f16 [%0], %1, %2, %3, {%5, %5, %5, %5}, p;\n\t}"
        :: "r"(d), "l"(a), "l"(b), "r"(idesc), "r"(en), "r"(0u) : "memory");
}
__device__ __forceinline__ uint64_t make_desc(uint32_t addr) {
    return ((uint64_t)2 << 61) | ((uint64_t)1 << 46) | ((uint64_t)64 << 32) |
           ((uint64_t)1 << 16) | ((uint64_t)(addr >> 4) & 0x3FFF);
}
static constexpr uint32_t IDESC_128x128 = 0x8200490u;
#endif  // HAS_TCGEN05

// ---------------------------------------------------------------------------
// Fused prep kernel: object mean + weight transpose/split
// ---------------------------------------------------------------------------
__global__ void prep_kernel(const float* __restrict__ states,
                            const float* __restrict__ W1,
                            const float* __restrict__ W2,
                            const float* __restrict__ W3) {
    if (blockIdx.x < 1024) {
        int lb = threadIdx.x >> 6;
        int d4 = threadIdx.x & 63;
        int b  = blockIdx.x * 4 + lb;
        const float4* src = (const float4*)(states + (size_t)b * OBJ * OBS);
        float4 acc = make_float4(0.f, 0.f, 0.f, 0.f);
#pragma unroll
        for (int o = 0; o < OBJ; ++o) {
            float4 v = src[o * (OBS / 4) + d4];
            acc.x += v.x; acc.y += v.y; acc.z += v.z; acc.w += v.w;
        }
        const float inv = 1.0f / OBJ;
        float vals[4] = {acc.x * inv, acc.y * inv, acc.z * inv, acc.w * inv};
        size_t base = (size_t)b * OBS + d4 * 4;
#pragma unroll
        for (int c = 0; c < 4; ++c) {
            __nv_bfloat16 hi, lo; split_bf16(vals[c], hi, lo);
            g_sbar_h[base + c] = hi; g_sbar_l[base + c] = lo;
        }
    } else {
        int r = blockIdx.x - 1024;       // 0..767
        int bz = r >> 8;
        int rem = r & 255;
        int bx = rem & 15, by = rem >> 4;
        const float* W; __nv_bfloat16 *Th, *Tl; int K, N;
        if (bz == 0)      { W = W1; Th = g_W1T_h; Tl = g_W1T_l; K = OBS; N = HID; }
        else if (bz == 1) { W = W2; Th = g_W2T_h; Tl = g_W2T_l; K = HID; N = HID; }
        else              { W = W3; Th = g_W3T_h; Tl = g_W3T_l; K = HID; N = OBS; }
        int k0 = by * 32, n0 = bx * 32;
        if (k0 >= K || n0 >= N) return;
        __shared__ float t[32][33];
        int tx = threadIdx.x & 31, ty = threadIdx.x >> 5;
#pragma unroll
        for (int i = 0; i < 4; ++i)
            t[ty + i * 8][tx] = W[(size_t)(k0 + ty + i * 8) * N + n0 + tx];
        __syncthreads();
#pragma unroll
        for (int i = 0; i < 4; ++i) {
            int n = ty + i * 8;
            float v = t[tx][n];
            __nv_bfloat16 hi, lo; split_bf16(v, hi, lo);
            size_t o = (size_t)(n0 + n) * K + k0 + tx;
            Th[o] = hi; Tl[o] = lo;
        }
    }
}

// ---------------------------------------------------------------------------
// tcgen05 bf16-split GEMM, producer/consumer pipeline + staged coalesced
// epilogue.
// MODE 1: h1 = relu(D + b1 + W1row/16) -> bf16 hi/lo
// MODE 2: z2 = D + b2 -> fp32
// MODE 3: out[(m*16 + blockIdx.z*nob + j)*256 + n] = D + b3, j = 0..nob-1
// ---------------------------------------------------------------------------
static constexpr int SM_TMEMPTR = 0;
static constexpr int SM_FULL    = 16;
static constexpr int SM_EMPTY   = 40;
static constexpr int SM_BIAS    = 64;
static constexpr int SM_W1ROWS  = 576;
static constexpr int SM_JROW    = 2688;
static constexpr int SM_TILES   = 4096;
static constexpr int TILE_BYTES = 128 * 128;
static constexpr int NSLOT      = 3;
static constexpr int STG_STRIDE = 132;   // fp32 staging row stride (16B-aligned)
static constexpr int GEMM_SMEM  = SM_TILES + NSLOT * 4 * TILE_BYTES;  // 200704

template <int MODE>
__global__ __launch_bounds__(256, 1)
void gemm_bf16s_kernel(const __nv_bfloat16* __restrict__ Ah,
                       const __nv_bfloat16* __restrict__ Al,
                       const __nv_bfloat16* __restrict__ BTh,
                       const __nv_bfloat16* __restrict__ BTl,
                       int Ktot, int Ntot,
                       const float* __restrict__ bias,
                       const int* __restrict__ action,
                       const float* __restrict__ W1,
                       float* __restrict__ outf,
                       __nv_bfloat16* __restrict__ outh,
                       __nv_bfloat16* __restrict__ outl,
                       int nob) {
#if HAS_TCGEN05
    extern __shared__ char sm[];
    const uint32_t smb = smem_u32(sm);
    const int tid = threadIdx.x;
    const int wid = tid >> 5;
    const int lid = tid & 31;
    const int m0 = blockIdx.y * 128;
    const int n0 = blockIdx.x * 128;

    float* s_bias = (float*)(sm + SM_BIAS);
    float* s_w1   = (float*)(sm + SM_W1ROWS);
    int*   s_jrow = (int*)(sm + SM_JROW);

    if (wid == 0) TCGEN05_ALLOC(smb + SM_TMEMPTR, 128);
    if (tid == 0) {
#pragma unroll
        for (int s = 0; s < NSLOT; ++s) {
            MBARRIER_INIT(smb + SM_FULL + s * 8, 256);
            MBARRIER_INIT(smb + SM_EMPTY + s * 8, 1);
        }
    }
    if (tid < 128) s_bias[tid] = bias[n0 + tid];
    if (MODE == 1) {
        for (int idx = tid; idx < 512; idx += 256)
            s_w1[idx] = W1[(size_t)(256 + (idx >> 7)) * HID + n0 + (idx & 127)];
        if (tid < 128) s_jrow[tid] = (action[m0 + tid] & 3) * 128;
    }
    __syncthreads();
    uint32_t tmem;
    asm volatile("ld.shared.b32 %0, [%1];" : "=r"(tmem) : "r"(smb + SM_TMEMPTR));

    const __nv_bfloat16* srcs[4] = {Ah, Al, BTh, BTl};
    const int row0s[4] = {m0, m0, n0, n0};
    const int NC = Ktot >> 6;

    auto load_stage = [&](int chunk, int slot) {
        const int kt = chunk << 6;
#pragma unroll
        for (int t = 0; t < 4; ++t) {
            uint32_t st = smb + SM_TILES + (uint32_t)(slot * 4 + t) * TILE_BYTES;
            const __nv_bfloat16* g = srcs[t];
            const int r0 = row0s[t];
#pragma unroll
            for (int ii = 0; ii < 4; ++ii) {
                int idx = tid + ii * 256;
                int r = idx >> 3, q = idx & 7;
                CP_ASYNC16(st + sw128(r * 128 + q * 16),
                           g + (size_t)(r0 + r) * Ktot + kt + q * 8);
            }
        }
        CP_MBAR_ARRIVE(smb + SM_FULL + slot * 8);
    };

#pragma unroll
    for (int c = 0; c < NSLOT; ++c) load_stage(c, c);

    const bool consumer = (wid == 0) && elect_one();
    for (int c = 0; c < NC; ++c) {
        const int s = c % NSLOT;
        const int k = c / NSLOT;
        if (consumer) {
            MBARRIER_WAIT_PARITY(smb + SM_FULL + s * 8, k & 1);
            FENCE_ASYNC_SHARED();
            uint32_t base = smb + SM_TILES + (uint32_t)(s * 4) * TILE_BYTES;
            uint64_t dAh = make_desc(base);
            uint64_t dAl = make_desc(base + TILE_BYTES);
            uint64_t dBh = make_desc(base + 2 * TILE_BYTES);
            uint64_t dBl = make_desc(base + 3 * TILE_BYTES);
#pragma unroll
            for (int ks = 0; ks < 4; ++ks) {
                mma_bf16_ss(tmem, dAh + ks * 2, dBh + ks * 2, IDESC_128x128,
                            (c > 0 || ks > 0) ? 1u : 0u);
                mma_bf16_ss(tmem, dAh + ks * 2, dBl + ks * 2, IDESC_128x128, 1u);
                mma_bf16_ss(tmem, dAl + ks * 2, dBh + ks * 2, IDESC_128x128, 1u);
            }
            TCGEN05_COMMIT(smb + SM_EMPTY + s * 8);
        }
        if (c + NSLOT < NC) {
            MBARRIER_WAIT_PARITY(smb + SM_EMPTY + s * 8, k & 1);
            load_stage(c + NSLOT, s);
        }
    }
    {
        const int cl = NC - 1;
        MBARRIER_WAIT_PARITY(smb + SM_EMPTY + (cl % NSLOT) * 8, (cl / NSLOT) & 1);
    }
    TCGEN05_FENCE_AFTER();

    // ---------------- staged, coalesced epilogue ----------------
    // Stage D (+bias) into smem [128][STG_STRIDE] fp32, reusing the (now
    // dead) tile region. TMEM ld: lane = row within the warp's 32-row band.
    float* s_d = (float*)(sm + SM_TILES);
    {
        const int wq = wid & 3, wc = wid >> 2;
        const int row = wq * 32 + lid;
#pragma unroll
        for (int cc = 0; cc < 2; ++cc) {
            const int cb = wc * 64 + cc * 32;
            uint32_t d[32];
            TCGEN05_LD_X32(d, tmem + cb);
            TCGEN05_WAIT_LD();
#pragma unroll
            for (int c = 0; c < 32; ++c)
                s_d[row * STG_STRIDE + cb + c] = __uint_as_float(d[c]) + s_bias[cb + c];
        }
    }
    __syncthreads();

    // Cooperative coalesced writes: consecutive tid -> consecutive addresses.
    if (MODE == 1) {
#pragma unroll
        for (int it = 0; it < 16; ++it) {
            int idx = it * 256 + tid;
            int row = idx >> 5, c4 = (idx & 31) * 4;
            int jr = s_jrow[row];
            float4 v = *(float4*)&s_d[row * STG_STRIDE + c4];
            float f0 = fmaxf(v.x + 0.0625f * s_w1[jr + c4 + 0], 0.f);
            float f1 = fmaxf(v.y + 0.0625f * s_w1[jr + c4 + 1], 0.f);
            float f2 = fmaxf(v.z + 0.0625f * s_w1[jr + c4 + 2], 0.f);
            float f3 = fmaxf(v.w + 0.0625f * s_w1[jr + c4 + 3], 0.f);
            __nv_bfloat16 h0, l0, h1, l1, h2, l2, h3, l3;
            split_bf16(f0, h0, l0); split_bf16(f1, h1, l1);
            split_bf16(f2, h2, l2); split_bf16(f3, h3, l3);
            __nv_bfloat162 hp0(h0, h1), hp1(h2, h3), lp0(l0, l1), lp1(l2, l3);
            uint2 hv = make_uint2(*(uint32_t*)&hp0, *(uint32_t*)&hp1);
            uint2 lv = make_uint2(*(uint32_t*)&lp0, *(uint32_t*)&lp1);
            size_t o = (size_t)(m0 + row) * Ntot + n0 + c4;
            *(uint2*)(outh + o) = hv;
            *(uint2*)(outl + o) = lv;
        }
    } else if (MODE == 2) {
#pragma unroll
        for (int it = 0; it < 16; ++it) {
            int idx = it * 256 + tid;
            int row = idx >> 5, c4 = (idx & 31) * 4;
            float4 v = *(float4*)&s_d[row * STG_STRIDE + c4];
            *(float4*)(outf + (size_t)(m0 + row) * Ntot + n0 + c4) = v;
        }
    } else {
#pragma unroll
        for (int it = 0; it < 16; ++it) {
            int idx = it * 256 + tid;
            int row = idx >> 5, c4 = (idx & 31) * 4;
            float4 v = *(float4*)&s_d[row * STG_STRIDE + c4];
            size_t base = (size_t)(m0 + row) * (OBJ * OBS) +
                          (size_t)(blockIdx.z * nob) * OBS + n0 + c4;
            for (int ob = 0; ob < nob; ++ob)
                *(float4*)(outf + base + (size_t)ob * OBS) = v;
        }
    }

    __syncthreads();
    if (wid == 0) {
        TCGEN05_RELINQ();
        TCGEN05_DEALLOC(tmem, 128);
    }
#else
    // Fallback for the non-sm_103a PTX pass (never selected on GB300).
    const int tid = threadIdx.x;
    const int m0 = blockIdx.y * 128;
    const int n0 = blockIdx.x * 128;
    for (int e = tid; e < 128 * 128; e += 256) {
        int r = e >> 7, c = e & 127;
        int m = m0 + r, n = n0 + c;
        float acc = 0.f;
        for (int k = 0; k < Ktot; ++k) {
            float a = __bfloat162float(Ah[(size_t)m * Ktot + k]) +
                      __bfloat162float(Al[(size_t)m * Ktot + k]);
            float b = __bfloat162float(BTh[(size_t)n * Ktot + k]) +
                      __bfloat162float(BTl[(size_t)n * Ktot + k]);
            acc += a * b;
        }
        acc += bias[n];
        if (MODE == 1) {
            int j = action[m] & 3;
            float v = fmaxf(acc + 0.0625f * W1[(size_t)(256 + j) * HID + n], 0.f);
            __nv_bfloat16 hi, lo; split_bf16(v, hi, lo);
            outh[(size_t)m * Ntot + n] = hi;
            outl[(size_t)m * Ntot + n] = lo;
        } else if (MODE == 2) {
            outf[(size_t)m * Ntot + n] = acc;
        } else {
            size_t base = (size_t)m * (OBJ * OBS) + (size_t)(blockIdx.z * nob) * OBS + n;
            for (int ob = 0; ob < nob; ++ob) outf[base + (size_t)ob * OBS] = acc;
        }
    }
#endif
}

// ---------------------------------------------------------------------------
// LayerNorm(512) + ReLU -> bf16 hi/lo
// ---------------------------------------------------------------------------
__device__ __forceinline__ float warp_sum(float v) {
#pragma unroll
    for (int o = 16; o > 0; o >>= 1) v += __shfl_xor_sync(0xffffffffu, v, o);
    return v;
}

__global__ void ln_relu_kernel(const float* __restrict__ g,
                               const float* __restrict__ b) {
    int row = blockIdx.x;
    int t = threadIdx.x;  // 128
    const float* x = g_z2 + (size_t)row * HID;
    float4 v = ((const float4*)x)[t];
    float s  = v.x + v.y + v.z + v.w;
    float ss = v.x * v.x + v.y * v.y + v.z * v.z + v.w * v.w;
    __shared__ float red[2][4];
    float sw = warp_sum(s), ssw = warp_sum(ss);
    int wid = t >> 5, lid = t & 31;
    if (lid == 0) { red[0][wid] = sw; red[1][wid] = ssw; }
    __syncthreads();
    float ts  = red[0][0] + red[0][1] + red[0][2] + red[0][3];
    float tss = red[1][0] + red[1][1] + red[1][2] + red[1][3];
    const float invn = 1.0f / HID;
    float mu = ts * invn;
    float var = tss * invn - mu * mu;
    float rs = rsqrtf(var + 1e-5f);
    float4 gv = ((const float4*)g)[t];
    float4 bv = ((const float4*)b)[t];
    float vals[4];
    vals[0] = fmaxf((v.x - mu) * rs * gv.x + bv.x, 0.f);
    vals[1] = fmaxf((v.y - mu) * rs * gv.y + bv.y, 0.f);
    vals[2] = fmaxf((v.z - mu) * rs * gv.z + bv.z, 0.f);
    vals[3] = fmaxf((v.w - mu) * rs * gv.w + bv.w, 0.f);
    size_t base = (size_t)row * HID + t * 4;
    __nv_bfloat16 h0, l0, h1, l1;
    split_bf16(vals[0], h0, l0); split_bf16(vals[1], h1, l1);
    *(__nv_bfloat162*)(g_h2_h + base) = __nv_bfloat162(h0, h1);
    *(__nv_bfloat162*)(g_h2_l + base) = __nv_bfloat162(l0, l1);
    split_bf16(vals[2], h0, l0); split_bf16(vals[3], h1, l1);
    *(__nv_bfloat162*)(g_h2_h + base + 2) = __nv_bfloat162(h0, h1);
    *(__nv_bfloat162*)(g_h2_l + base + 2) = __nv_bfloat162(l0, l1);
}

// ---------------------------------------------------------------------------
extern "C" void kernel_launch(void* const* d_in, const int* in_sizes, int n_in,
                              void* d_out, int out_size) {
    const float* states = (const float*)d_in[0];
    const int*   action = (const int*)d_in[1];
    const float* W1     = (const float*)d_in[2];
    const float* b1     = (const float*)d_in[3];
    const float* W2     = (const float*)d_in[4];
    const float* b2     = (const float*)d_in[5];
    const float* W3     = (const float*)d_in[6];
    const float* b3     = (const float*)d_in[7];
    const float* ln_g   = (const float*)d_in[8];
    const float* ln_b   = (const float*)d_in[9];
    float* out = (float*)d_out;

    __nv_bfloat16 *sbh, *sbl, *h1h, *h1l, *h2h, *h2l;
    __nv_bfloat16 *w1h, *w1l, *w2h, *w2l, *w3h, *w3l;
    float* z2p;
    cudaGetSymbolAddress((void**)&sbh, g_sbar_h);
    cudaGetSymbolAddress((void**)&sbl, g_sbar_l);
    cudaGetSymbolAddress((void**)&h1h, g_h1_h);
    cudaGetSymbolAddress((void**)&h1l, g_h1_l);
    cudaGetSymbolAddress((void**)&h2h, g_h2_h);
    cudaGetSymbolAddress((void**)&h2l, g_h2_l);
    cudaGetSymbolAddress((void**)&w1h, g_W1T_h);
    cudaGetSymbolAddress((void**)&w1l, g_W1T_l);
    cudaGetSymbolAddress((void**)&w2h, g_W2T_h);
    cudaGetSymbolAddress((void**)&w2l, g_W2T_l);
    cudaGetSymbolAddress((void**)&w3h, g_W3T_h);
    cudaGetSymbolAddress((void**)&w3l, g_W3T_l);
    cudaGetSymbolAddress((void**)&z2p, g_z2);

    cudaFuncSetAttribute(gemm_bf16s_kernel<1>,
                         cudaFuncAttributeMaxDynamicSharedMemorySize, GEMM_SMEM);
    cudaFuncSetAttribute(gemm_bf16s_kernel<2>,
                         cudaFuncAttributeMaxDynamicSharedMemorySize, GEMM_SMEM);
    cudaFuncSetAttribute(gemm_bf16s_kernel<3>,
                         cudaFuncAttributeMaxDynamicSharedMemorySize, GEMM_SMEM);

    prep_kernel<<<1792, 256>>>(states, W1, W2, W3);
    gemm_bf16s_kernel<1><<<dim3(HID / 128, BATCH / 128), 256, GEMM_SMEM>>>(
        sbh, sbl, w1h, w1l, OBS, HID, b1, action, W1, nullptr, h1h, h1l, 0);
    gemm_bf16s_kernel<2><<<dim3(HID / 128, BATCH / 128), 256, GEMM_SMEM>>>(
        h1h, h1l, w2h, w2l, HID, HID, b2, nullptr, nullptr, z2p, nullptr, nullptr, 0);
    ln_relu_kernel<<<BATCH, 128>>>(ln_g, ln_b);
    gemm_bf16s_kernel<3><<<dim3(OBS / 128, BATCH / 128, 2), 256, GEMM_SMEM>>>(
        h2h, h2l, w3h, w3l, HID, OBS, b3, nullptr, nullptr, out, nullptr, nullptr, 8);
}

// round 8
// speedup vs baseline: 4.9022x; 1.0618x over previous
#include <cuda_runtime.h>
#include <cuda_bf16.h>
#include <cstdint>
#include <math.h>

#define BATCH 4096
#define OBJ   16
#define OBS   256
#define HID   512

#if defined(__CUDA_ARCH__) && (defined(__CUDA_ARCH_FEAT_SM103_ALL) || \
    (defined(__CUDA_ARCH_SPECIFIC__) && __CUDA_ARCH_SPECIFIC__ == 1030) || \
    (defined(__CUDA_ARCH_FAMILY_SPECIFIC__) && __CUDA_ARCH_FAMILY_SPECIFIC__ == 1030))
#define HAS_TCGEN05 1
#else
#define HAS_TCGEN05 0
#endif

// ---------------------------------------------------------------------------
// Scratch
// ---------------------------------------------------------------------------
__device__ __nv_bfloat16 g_sbar_h[BATCH * OBS], g_sbar_l[BATCH * OBS];
__device__ __nv_bfloat16 g_h1_h[BATCH * HID], g_h1_l[BATCH * HID];
__device__ __nv_bfloat16 g_h2_h[BATCH * HID], g_h2_l[BATCH * HID];
__device__ __nv_bfloat16 g_W1T_h[HID * OBS], g_W1T_l[HID * OBS];
__device__ __nv_bfloat16 g_W2T_h[HID * HID], g_W2T_l[HID * HID];
__device__ __nv_bfloat16 g_W3T_h[OBS * HID], g_W3T_l[OBS * HID];
// LN partial exchange (gemm2): 32 row-bands x 4 n-CTAs x 128 rows x (sum, sumsq)
__device__ float2 g_part[32][4][128];
__device__ int    g_cnt[32];

// ---------------------------------------------------------------------------
// helpers
// ---------------------------------------------------------------------------
__device__ __forceinline__ uint32_t smem_u32(const void* p) {
    uint32_t a;
    asm("{ .reg .u64 t; cvta.to.shared.u64 t, %1; cvt.u32.u64 %0, t; }"
        : "=r"(a) : "l"(p));
    return a;
}
__device__ __forceinline__ uint32_t sw128(uint32_t off) {
    return off ^ ((off >> 3) & 0x70);
}
__device__ __forceinline__ void split_bf16(float v, __nv_bfloat16& hi, __nv_bfloat16& lo) {
    hi = __float2bfloat16(v);
    lo = __float2bfloat16(v - __bfloat162float(hi));
}

#define CP_ASYNC16(smem_a, gptr)                                               \
    asm volatile("cp.async.cg.shared.global [%0], [%1], 16;"                   \
                 :: "r"((uint32_t)(smem_a)), "l"(gptr) : "memory")
#define CP_MBAR_ARRIVE(mbar)                                                   \
    asm volatile("cp.async.mbarrier.arrive.noinc.shared.b64 [%0];"             \
                 :: "r"((uint32_t)(mbar)) : "memory")
#define MBARRIER_INIT(mbar, cnt)                                               \
    asm volatile("mbarrier.init.shared.b64 [%0], %1;"                          \
                 :: "r"((uint32_t)(mbar)), "r"((uint32_t)(cnt)) : "memory")
#define MBARRIER_WAIT_PARITY(mbar_a, par_a) do {                               \
    uint32_t _mb = (uint32_t)(mbar_a);                                         \
    uint32_t _pa = (uint32_t)(par_a);                                          \
    uint32_t _done;                                                            \
    asm volatile("{\n\t.reg .pred p;\n\t"                                      \
        "mbarrier.try_wait.parity.acquire.cta.shared::cta.b64 p, [%1], %2;\n\t"\
        "selp.b32 %0, 1, 0, p;\n\t}"                                           \
        : "=r"(_done) : "r"(_mb), "r"(_pa) : "memory");                        \
    if (!_done) {                                                              \
        asm volatile("{\n\t.reg .pred P1;\n\t"                                 \
            "WL_%=:\n\t"                                                       \
            "mbarrier.try_wait.parity.acquire.cta.shared::cta.b64 P1, [%0], %1, 0x989680;\n\t" \
            "@P1 bra.uni WD_%=;\n\t"                                           \
            "bra.uni WL_%=;\n\t"                                               \
            "WD_%=:\n\t}" :: "r"(_mb), "r"(_pa) : "memory");                   \
    }                                                                          \
} while (0)

#if HAS_TCGEN05
__device__ __forceinline__ uint32_t elect_one() {
    uint32_t pred;
    asm volatile("{\n\t.reg .pred p;\n\telect.sync _|p, 0xFFFFFFFF;\n\t"
                 "selp.b32 %0, 1, 0, p;\n\t}" : "=r"(pred));
    return pred;
}
#define TCGEN05_ALLOC(sm_addr, ncols)                                          \
    asm volatile("tcgen05.alloc.cta_group::1.sync.aligned.shared::cta.b32 [%0], %1;" \
                 :: "r"((uint32_t)(sm_addr)), "r"((uint32_t)(ncols)) : "memory")
#define TCGEN05_DEALLOC(tmem, ncols)                                           \
    asm volatile("tcgen05.dealloc.cta_group::1.sync.aligned.b32 %0, %1;"       \
                 :: "r"(tmem), "r"((uint32_t)(ncols)))
#define TCGEN05_RELINQ()                                                       \
    asm volatile("tcgen05.relinquish_alloc_permit.cta_group::1.sync.aligned;")
#define TCGEN05_COMMIT(mbar)                                                   \
    asm volatile("tcgen05.commit.cta_group::1.mbarrier::arrive::one.shared::cluster.b64 [%0];" \
                 :: "r"((uint32_t)(mbar)) : "memory")
#define TCGEN05_WAIT_LD() asm volatile("tcgen05.wait::ld.sync.aligned;" ::: "memory")
#define TCGEN05_FENCE_AFTER() asm volatile("tcgen05.fence::after_thread_sync;" ::: "memory")
#define FENCE_ASYNC_SHARED() asm volatile("fence.proxy.async.shared::cta;" ::: "memory")

#define TCGEN05_LD_X32(r, tmem_addr)                                           \
    asm volatile("tcgen05.ld.sync.aligned.32x32b.x32.b32 "                     \
        "{%0, %1, %2, %3, %4, %5, %6, %7, "                                    \
        " %8, %9, %10, %11, %12, %13, %14, %15, "                              \
        " %16, %17, %18, %19, %20, %21, %22, %23, "                            \
        " %24, %25, %26, %27, %28, %29, %30, %31}, [%32];"                     \
        : "=r"((r)[0]),  "=r"((r)[1]),  "=r"((r)[2]),  "=r"((r)[3]),           \
          "=r"((r)[4]),  "=r"((r)[5]),  "=r"((r)[6]),  "=r"((r)[7]),           \
          "=r"((r)[8]),  "=r"((r)[9]),  "=r"((r)[10]), "=r"((r)[11]),          \
          "=r"((r)[12]), "=r"((r)[13]), "=r"((r)[14]), "=r"((r)[15]),          \
          "=r"((r)[16]), "=r"((r)[17]), "=r"((r)[18]), "=r"((r)[19]),          \
          "=r"((r)[20]), "=r"((r)[21]), "=r"((r)[22]), "=r"((r)[23]),          \
          "=r"((r)[24]), "=r"((r)[25]), "=r"((r)[26]), "=r"((r)[27]),          \
          "=r"((r)[28]), "=r"((r)[29]), "=r"((r)[30]), "=r"((r)[31])           \
        : "r"(tmem_addr))

__device__ __forceinline__ void mma_bf16_ss(uint32_t d, uint64_t a, uint64_t b,
                                            uint32_t idesc, uint32_t en) {
    asm volatile(
        "{\n\t.reg .pred p;\n\tsetp.ne.u32 p, %4, 0;\n\t"
        "tcgen05.mma.cta_group::1.kind::f16 [%0], %1, %2, %3, {%5, %5, %5, %5}, p;\n\t}"
        :: "r"(d), "l"(a), "l"(b), "r"(idesc), "r"(en), "r"(0u) : "memory");
}
__device__ __forceinline__ uint64_t make_desc(uint32_t addr) {
    return ((uint64_t)2 << 61) | ((uint64_t)1 << 46) | ((uint64_t)64 << 32) |
           ((uint64_t)1 << 16) | ((uint64_t)(addr >> 4) & 0x3FFF);
}
static constexpr uint32_t IDESC_128x128 = 0x8200490u;
#endif  // HAS_TCGEN05

// ---------------------------------------------------------------------------
// Fused prep kernel: object mean + weight transpose/split + g_cnt reset
// ---------------------------------------------------------------------------
__global__ void prep_kernel(const float* __restrict__ states,
                            const float* __restrict__ W1,
                            const float* __restrict__ W2,
                            const float* __restrict__ W3) {
    if (blockIdx.x == 0 && threadIdx.x < 32) g_cnt[threadIdx.x] = 0;
    if (blockIdx.x < 1024) {
        int lb = threadIdx.x >> 6;
        int d4 = threadIdx.x & 63;
        int b  = blockIdx.x * 4 + lb;
        const float4* src = (const float4*)(states + (size_t)b * OBJ * OBS);
        float4 acc = make_float4(0.f, 0.f, 0.f, 0.f);
#pragma unroll
        for (int o = 0; o < OBJ; ++o) {
            float4 v = src[o * (OBS / 4) + d4];
            acc.x += v.x; acc.y += v.y; acc.z += v.z; acc.w += v.w;
        }
        const float inv = 1.0f / OBJ;
        float vals[4] = {acc.x * inv, acc.y * inv, acc.z * inv, acc.w * inv};
        size_t base = (size_t)b * OBS + d4 * 4;
#pragma unroll
        for (int c = 0; c < 4; ++c) {
            __nv_bfloat16 hi, lo; split_bf16(vals[c], hi, lo);
            g_sbar_h[base + c] = hi; g_sbar_l[base + c] = lo;
        }
    } else {
        int r = blockIdx.x - 1024;
        int bz = r >> 8;
        int rem = r & 255;
        int bx = rem & 15, by = rem >> 4;
        const float* W; __nv_bfloat16 *Th, *Tl; int K, N;
        if (bz == 0)      { W = W1; Th = g_W1T_h; Tl = g_W1T_l; K = OBS; N = HID; }
        else if (bz == 1) { W = W2; Th = g_W2T_h; Tl = g_W2T_l; K = HID; N = HID; }
        else              { W = W3; Th = g_W3T_h; Tl = g_W3T_l; K = HID; N = OBS; }
        int k0 = by * 32, n0 = bx * 32;
        if (k0 >= K || n0 >= N) return;
        __shared__ float t[32][33];
        int tx = threadIdx.x & 31, ty = threadIdx.x >> 5;
#pragma unroll
        for (int i = 0; i < 4; ++i)
            t[ty + i * 8][tx] = W[(size_t)(k0 + ty + i * 8) * N + n0 + tx];
        __syncthreads();
#pragma unroll
        for (int i = 0; i < 4; ++i) {
            int n = ty + i * 8;
            float v = t[tx][n];
            __nv_bfloat16 hi, lo; split_bf16(v, hi, lo);
            size_t o = (size_t)(n0 + n) * K + k0 + tx;
            Th[o] = hi; Tl[o] = lo;
        }
    }
}

// ---------------------------------------------------------------------------
// smem layout
// ---------------------------------------------------------------------------
static constexpr int SM_TMEMPTR = 0;
static constexpr int SM_FULL    = 16;
static constexpr int SM_EMPTY   = 40;
static constexpr int SM_BIAS    = 64;     // 128 f32
static constexpr int SM_W1ROWS  = 576;    // 512 f32 (MODE 1) / s_g (gemm2)
static constexpr int SM_LNB     = 1088;   // 128 f32 (gemm2)
static constexpr int SM_MU      = 1600;   // 128 f32 (gemm2)
static constexpr int SM_RS      = 2112;   // 128 f32 (gemm2)
static constexpr int SM_JROW    = 2624;   // 128 int (MODE 1)
static constexpr int SM_TILES   = 4096;
static constexpr int TILE_BYTES = 128 * 128;
static constexpr int NSLOT      = 3;
static constexpr int STG_STRIDE = 132;
static constexpr int GEMM_SMEM  = SM_TILES + NSLOT * 4 * TILE_BYTES;  // 200704

// ---------------------------------------------------------------------------
// GEMM mainloop (shared by all GEMM kernels): producer/consumer 3-slot
// cp.async pipeline feeding tcgen05; stages D(+bias) into s_d on completion.
// ---------------------------------------------------------------------------
#if HAS_TCGEN05
__device__ __forceinline__ void gemm_mainloop_stage(
    const char* sm, uint32_t smb, int tid, int wid, int lid,
    const __nv_bfloat16* Ah, const __nv_bfloat16* Al,
    const __nv_bfloat16* BTh, const __nv_bfloat16* BTl,
    int m0, int n0, int Ktot) {
    if (wid == 0) TCGEN05_ALLOC(smb + SM_TMEMPTR, 128);
    if (tid == 0) {
#pragma unroll
        for (int s = 0; s < NSLOT; ++s) {
            MBARRIER_INIT(smb + SM_FULL + s * 8, 256);
            MBARRIER_INIT(smb + SM_EMPTY + s * 8, 1);
        }
    }
    __syncthreads();
    uint32_t tmem;
    asm volatile("ld.shared.b32 %0, [%1];" : "=r"(tmem) : "r"(smb + SM_TMEMPTR));

    const __nv_bfloat16* srcs[4] = {Ah, Al, BTh, BTl};
    const int row0s[4] = {m0, m0, n0, n0};
    const int NC = Ktot >> 6;

    auto load_stage = [&](int chunk, int slot) {
        const int kt = chunk << 6;
#pragma unroll
        for (int t = 0; t < 4; ++t) {
            uint32_t st = smb + SM_TILES + (uint32_t)(slot * 4 + t) * TILE_BYTES;
            const __nv_bfloat16* g = srcs[t];
            const int r0 = row0s[t];
#pragma unroll
            for (int ii = 0; ii < 4; ++ii) {
                int idx = tid + ii * 256;
                int r = idx >> 3, q = idx & 7;
                CP_ASYNC16(st + sw128(r * 128 + q * 16),
                           g + (size_t)(r0 + r) * Ktot + kt + q * 8);
            }
        }
        CP_MBAR_ARRIVE(smb + SM_FULL + slot * 8);
    };

#pragma unroll
    for (int c = 0; c < NSLOT; ++c) load_stage(c, c);

    const bool consumer = (wid == 0) && elect_one();
    for (int c = 0; c < NC; ++c) {
        const int s = c % NSLOT;
        const int k = c / NSLOT;
        if (consumer) {
            MBARRIER_WAIT_PARITY(smb + SM_FULL + s * 8, k & 1);
            FENCE_ASYNC_SHARED();
            uint32_t base = smb + SM_TILES + (uint32_t)(s * 4) * TILE_BYTES;
            uint64_t dAh = make_desc(base);
            uint64_t dAl = make_desc(base + TILE_BYTES);
            uint64_t dBh = make_desc(base + 2 * TILE_BYTES);
            uint64_t dBl = make_desc(base + 3 * TILE_BYTES);
#pragma unroll
            for (int ks = 0; ks < 4; ++ks) {
                mma_bf16_ss(tmem, dAh + ks * 2, dBh + ks * 2, IDESC_128x128,
                            (c > 0 || ks > 0) ? 1u : 0u);
                mma_bf16_ss(tmem, dAh + ks * 2, dBl + ks * 2, IDESC_128x128, 1u);
                mma_bf16_ss(tmem, dAl + ks * 2, dBh + ks * 2, IDESC_128x128, 1u);
            }
            TCGEN05_COMMIT(smb + SM_EMPTY + s * 8);
        }
        if (c + NSLOT < NC) {
            MBARRIER_WAIT_PARITY(smb + SM_EMPTY + s * 8, k & 1);
            load_stage(c + NSLOT, s);
        }
    }
    {
        const int cl = NC - 1;
        MBARRIER_WAIT_PARITY(smb + SM_EMPTY + (cl % NSLOT) * 8, (cl / NSLOT) & 1);
    }
    TCGEN05_FENCE_AFTER();

    // stage D (+bias) into s_d
    float* s_d = (float*)(sm + SM_TILES);
    const float* s_bias = (const float*)(sm + SM_BIAS);
    {
        const int wq = wid & 3, wc = wid >> 2;
        const int row = wq * 32 + lid;
#pragma unroll
        for (int cc = 0; cc < 2; ++cc) {
            const int cb = wc * 64 + cc * 32;
            uint32_t d[32];
            TCGEN05_LD_X32(d, tmem + cb);
            TCGEN05_WAIT_LD();
#pragma unroll
            for (int c = 0; c < 32; ++c)
                s_d[row * STG_STRIDE + cb + c] = __uint_as_float(d[c]) + s_bias[cb + c];
        }
    }
    __syncthreads();
    if (wid == 0) {
        TCGEN05_RELINQ();
        TCGEN05_DEALLOC(tmem, 128);
    }
}
#else
// Fallback mainloop for the non-sm_103a PTX pass (never selected on GB300).
__device__ __forceinline__ void gemm_mainloop_stage(
    const char* sm, uint32_t smb, int tid, int wid, int lid,
    const __nv_bfloat16* Ah, const __nv_bfloat16* Al,
    const __nv_bfloat16* BTh, const __nv_bfloat16* BTl,
    int m0, int n0, int Ktot) {
    float* s_d = (float*)(sm + SM_TILES);
    const float* s_bias = (const float*)(sm + SM_BIAS);
    __syncthreads();
    for (int e = tid; e < 128 * 128; e += 256) {
        int r = e >> 7, c = e & 127;
        float acc = 0.f;
        for (int k = 0; k < Ktot; ++k) {
            float a = __bfloat162float(Ah[(size_t)(m0 + r) * Ktot + k]) +
                      __bfloat162float(Al[(size_t)(m0 + r) * Ktot + k]);
            float b = __bfloat162float(BTh[(size_t)(n0 + c) * Ktot + k]) +
                      __bfloat162float(BTl[(size_t)(n0 + c) * Ktot + k]);
            acc += a * b;
        }
        s_d[r * STG_STRIDE + c] = acc + s_bias[c];
    }
    __syncthreads();
}
#endif

// ---------------------------------------------------------------------------
// GEMM1 (h1) / GEMM3 (broadcast output)
// ---------------------------------------------------------------------------
template <int MODE>
__global__ __launch_bounds__(256, 1)
void gemm_bf16s_kernel(const __nv_bfloat16* __restrict__ Ah,
                       const __nv_bfloat16* __restrict__ Al,
                       const __nv_bfloat16* __restrict__ BTh,
                       const __nv_bfloat16* __restrict__ BTl,
                       int Ktot, int Ntot,
                       const float* __restrict__ bias,
                       const int* __restrict__ action,
                       const float* __restrict__ W1,
                       float* __restrict__ outf,
                       __nv_bfloat16* __restrict__ outh,
                       __nv_bfloat16* __restrict__ outl,
                       int nob) {
    extern __shared__ char sm[];
    const uint32_t smb = smem_u32(sm);
    const int tid = threadIdx.x;
    const int wid = tid >> 5;
    const int lid = tid & 31;
    const int m0 = blockIdx.y * 128;
    const int n0 = blockIdx.x * 128;

    float* s_bias = (float*)(sm + SM_BIAS);
    float* s_w1   = (float*)(sm + SM_W1ROWS);
    int*   s_jrow = (int*)(sm + SM_JROW);

    if (tid < 128) s_bias[tid] = bias[n0 + tid];
    if (MODE == 1) {
        for (int idx = tid; idx < 512; idx += 256)
            s_w1[idx] = W1[(size_t)(256 + (idx >> 7)) * HID + n0 + (idx & 127)];
        if (tid < 128) s_jrow[tid] = (action[m0 + tid] & 3) * 128;
    }

    gemm_mainloop_stage(sm, smb, tid, wid, lid, Ah, Al, BTh, BTl, m0, n0, Ktot);

    float* s_d = (float*)(sm + SM_TILES);
    if (MODE == 1) {
#pragma unroll
        for (int it = 0; it < 16; ++it) {
            int idx = it * 256 + tid;
            int row = idx >> 5, c4 = (idx & 31) * 4;
            int jr = s_jrow[row];
            float4 v = *(float4*)&s_d[row * STG_STRIDE + c4];
            float f0 = fmaxf(v.x + 0.0625f * s_w1[jr + c4 + 0], 0.f);
            float f1 = fmaxf(v.y + 0.0625f * s_w1[jr + c4 + 1], 0.f);
            float f2 = fmaxf(v.z + 0.0625f * s_w1[jr + c4 + 2], 0.f);
            float f3 = fmaxf(v.w + 0.0625f * s_w1[jr + c4 + 3], 0.f);
            __nv_bfloat16 h0, l0, h1, l1, h2, l2, h3, l3;
            split_bf16(f0, h0, l0); split_bf16(f1, h1, l1);
            split_bf16(f2, h2, l2); split_bf16(f3, h3, l3);
            __nv_bfloat162 hp0(h0, h1), hp1(h2, h3), lp0(l0, l1), lp1(l2, l3);
            uint2 hv = make_uint2(*(uint32_t*)&hp0, *(uint32_t*)&hp1);
            uint2 lv = make_uint2(*(uint32_t*)&lp0, *(uint32_t*)&lp1);
            size_t o = (size_t)(m0 + row) * Ntot + n0 + c4;
            *(uint2*)(outh + o) = hv;
            *(uint2*)(outl + o) = lv;
        }
    } else {
#pragma unroll
        for (int it = 0; it < 16; ++it) {
            int idx = it * 256 + tid;
            int row = idx >> 5, c4 = (idx & 31) * 4;
            float4 v = *(float4*)&s_d[row * STG_STRIDE + c4];
            size_t base = (size_t)(m0 + row) * (OBJ * OBS) +
                          (size_t)(blockIdx.z * nob) * OBS + n0 + c4;
            for (int ob = 0; ob < nob; ++ob)
                *(float4*)(outf + base + (size_t)ob * OBS) = v;
        }
    }
}

// ---------------------------------------------------------------------------
// GEMM2 + fused LayerNorm/ReLU. 4 n-CTAs of one 128-row band exchange per-row
// (sum, sumsq) partials via global memory + a co-residency spin barrier
// (128 CTAs x 200KB smem = 1 CTA/SM, grid < #SMs => single wave, no deadlock).
// ---------------------------------------------------------------------------
__global__ __launch_bounds__(256, 1)
void gemm2_ln_kernel(const __nv_bfloat16* __restrict__ Ah,
                     const __nv_bfloat16* __restrict__ Al,
                     const __nv_bfloat16* __restrict__ BTh,
                     const __nv_bfloat16* __restrict__ BTl,
                     const float* __restrict__ bias,
                     const float* __restrict__ ln_g,
                     const float* __restrict__ ln_b,
                     __nv_bfloat16* __restrict__ outh,
                     __nv_bfloat16* __restrict__ outl) {
    extern __shared__ char sm[];
    const uint32_t smb = smem_u32(sm);
    const int tid = threadIdx.x;
    const int wid = tid >> 5;
    const int lid = tid & 31;
    const int bx = blockIdx.x;        // n-CTA 0..3
    const int by = blockIdx.y;        // row band 0..31
    const int m0 = by * 128;
    const int n0 = bx * 128;

    float* s_bias = (float*)(sm + SM_BIAS);
    float* s_g    = (float*)(sm + SM_W1ROWS);
    float* s_b    = (float*)(sm + SM_LNB);
    float* s_mu   = (float*)(sm + SM_MU);
    float* s_rs   = (float*)(sm + SM_RS);

    if (tid < 128) {
        s_bias[tid] = bias[n0 + tid];
        s_g[tid]    = ln_g[n0 + tid];
        s_b[tid]    = ln_b[n0 + tid];
    }

    gemm_mainloop_stage(sm, smb, tid, wid, lid, Ah, Al, BTh, BTl, m0, n0, HID);

    float* s_d = (float*)(sm + SM_TILES);

    // per-row partial (sum, sumsq) over this CTA's 128 cols: 2 threads/row
    {
        int prow = tid >> 1, ph = tid & 1;
        float s = 0.f, ss = 0.f;
#pragma unroll
        for (int i = 0; i < 16; ++i) {
            float4 v = *(float4*)&s_d[prow * STG_STRIDE + ph * 64 + i * 4];
            s  += v.x + v.y + v.z + v.w;
            ss += v.x * v.x + v.y * v.y + v.z * v.z + v.w * v.w;
        }
        s  += __shfl_xor_sync(0xffffffffu, s, 1);
        ss += __shfl_xor_sync(0xffffffffu, ss, 1);
        if (ph == 0) g_part[by][bx][prow] = make_float2(s, ss);
    }
    __syncthreads();
    // release partials, arrive, spin for the band's 4 CTAs
    if (tid == 0) {
        __threadfence();
        atomicAdd(&g_cnt[by], 1);
        while (atomicAdd(&g_cnt[by], 0) < 4) {}
        __threadfence();
    }
    __syncthreads();
    // combine 4 partial blocks -> mu, rsqrt per row
    if (tid < 128) {
        float ts = 0.f, tss = 0.f;
#pragma unroll
        for (int r = 0; r < 4; ++r) {
            float2 p = __ldcg(&g_part[by][r][tid]);
            ts += p.x; tss += p.y;
        }
        const float invn = 1.0f / HID;
        float mu = ts * invn;
        float var = tss * invn - mu * mu;
        s_mu[tid] = mu;
        s_rs[tid] = rsqrtf(var + 1e-5f);
    }
    __syncthreads();

    // coalesced LN + ReLU + bf16-split stores
#pragma unroll
    for (int it = 0; it < 16; ++it) {
        int idx = it * 256 + tid;
        int row = idx >> 5, c4 = (idx & 31) * 4;
        float mu = s_mu[row], rs = s_rs[row];
        float4 v = *(float4*)&s_d[row * STG_STRIDE + c4];
        float f0 = fmaxf((v.x - mu) * rs * s_g[c4 + 0] + s_b[c4 + 0], 0.f);
        float f1 = fmaxf((v.y - mu) * rs * s_g[c4 + 1] + s_b[c4 + 1], 0.f);
        float f2 = fmaxf((v.z - mu) * rs * s_g[c4 + 2] + s_b[c4 + 2], 0.f);
        float f3 = fmaxf((v.w - mu) * rs * s_g[c4 + 3] + s_b[c4 + 3], 0.f);
        __nv_bfloat16 h0, l0, h1, l1, h2, l2, h3, l3;
        split_bf16(f0, h0, l0); split_bf16(f1, h1, l1);
        split_bf16(f2, h2, l2); split_bf16(f3, h3, l3);
        __nv_bfloat162 hp0(h0, h1), hp1(h2, h3), lp0(l0, l1), lp1(l2, l3);
        uint2 hv = make_uint2(*(uint32_t*)&hp0, *(uint32_t*)&hp1);
        uint2 lv = make_uint2(*(uint32_t*)&lp0, *(uint32_t*)&lp1);
        size_t o = (size_t)(m0 + row) * HID + n0 + c4;
        *(uint2*)(outh + o) = hv;
        *(uint2*)(outl + o) = lv;
    }
}

// ---------------------------------------------------------------------------
extern "C" void kernel_launch(void* const* d_in, const int* in_sizes, int n_in,
                              void* d_out, int out_size) {
    const float* states = (const float*)d_in[0];
    const int*   action = (const int*)d_in[1];
    const float* W1     = (const float*)d_in[2];
    const float* b1     = (const float*)d_in[3];
    const float* W2     = (const float*)d_in[4];
    const float* b2     = (const float*)d_in[5];
    const float* W3     = (const float*)d_in[6];
    const float* b3     = (const float*)d_in[7];
    const float* ln_g   = (const float*)d_in[8];
    const float* ln_b   = (const float*)d_in[9];
    float* out = (float*)d_out;

    __nv_bfloat16 *sbh, *sbl, *h1h, *h1l, *h2h, *h2l;
    __nv_bfloat16 *w1h, *w1l, *w2h, *w2l, *w3h, *w3l;
    cudaGetSymbolAddress((void**)&sbh, g_sbar_h);
    cudaGetSymbolAddress((void**)&sbl, g_sbar_l);
    cudaGetSymbolAddress((void**)&h1h, g_h1_h);
    cudaGetSymbolAddress((void**)&h1l, g_h1_l);
    cudaGetSymbolAddress((void**)&h2h, g_h2_h);
    cudaGetSymbolAddress((void**)&h2l, g_h2_l);
    cudaGetSymbolAddress((void**)&w1h, g_W1T_h);
    cudaGetSymbolAddress((void**)&w1l, g_W1T_l);
    cudaGetSymbolAddress((void**)&w2h, g_W2T_h);
    cudaGetSymbolAddress((void**)&w2l, g_W2T_l);
    cudaGetSymbolAddress((void**)&w3h, g_W3T_h);
    cudaGetSymbolAddress((void**)&w3l, g_W3T_l);

    cudaFuncSetAttribute(gemm_bf16s_kernel<1>,
                         cudaFuncAttributeMaxDynamicSharedMemorySize, GEMM_SMEM);
    cudaFuncSetAttribute(gemm_bf16s_kernel<3>,
                         cudaFuncAttributeMaxDynamicSharedMemorySize, GEMM_SMEM);
    cudaFuncSetAttribute(gemm2_ln_kernel,
                         cudaFuncAttributeMaxDynamicSharedMemorySize, GEMM_SMEM);

    // 0) fused prep: object mean + weight transpose/split + g_cnt reset
    prep_kernel<<<1792, 256>>>(states, W1, W2, W3);
    // 1) h1 = relu(sbar @ W1[:256] + b1 + W1[256+a%4]/16) -> bf16 hi/lo
    gemm_bf16s_kernel<1><<<dim3(HID / 128, BATCH / 128), 256, GEMM_SMEM>>>(
        sbh, sbl, w1h, w1l, OBS, HID, b1, action, W1, nullptr, h1h, h1l, 0);
    // 2) h2 = relu(LN(h1 @ W2 + b2)) fused -> bf16 hi/lo
    gemm2_ln_kernel<<<dim3(HID / 128, BATCH / 128), 256, GEMM_SMEM>>>(
        h1h, h1l, w2h, w2l, b2, ln_g, ln_b, h2h, h2l);
    // 3) out = broadcast_obj(h2 @ W3 + b3), object dim split across grid.z
    gemm_bf16s_kernel<3><<<dim3(OBS / 128, BATCH / 128, 2), 256, GEMM_SMEM>>>(
        h2h, h2l, w3h, w3l, HID, OBS, b3, nullptr, nullptr, out, nullptr, nullptr, 8);
}

// round 10
// speedup vs baseline: 5.0909x; 1.0385x over previous
#include <cuda_runtime.h>
#include <cuda_bf16.h>
#include <cstdint>
#include <math.h>

#define BATCH 4096
#define OBJ   16
#define OBS   256
#define HID   512

#if defined(__CUDA_ARCH__) && (defined(__CUDA_ARCH_FEAT_SM103_ALL) || \
    (defined(__CUDA_ARCH_SPECIFIC__) && __CUDA_ARCH_SPECIFIC__ == 1030) || \
    (defined(__CUDA_ARCH_FAMILY_SPECIFIC__) && __CUDA_ARCH_FAMILY_SPECIFIC__ == 1030))
#define HAS_TCGEN05 1
#else
#define HAS_TCGEN05 0
#endif

// ---------------------------------------------------------------------------
// Scratch
// ---------------------------------------------------------------------------
__device__ __nv_bfloat16 g_sbar_h[BATCH * OBS], g_sbar_l[BATCH * OBS];
__device__ __nv_bfloat16 g_h1_h[BATCH * HID], g_h1_l[BATCH * HID];
__device__ __nv_bfloat16 g_h2_h[BATCH * HID], g_h2_l[BATCH * HID];
__device__ __nv_bfloat16 g_W1T_h[HID * OBS], g_W1T_l[HID * OBS];
__device__ __nv_bfloat16 g_W2T_h[HID * HID], g_W2T_l[HID * HID];
__device__ __nv_bfloat16 g_W3T_h[OBS * HID], g_W3T_l[OBS * HID];
// LN partial exchange + phase barriers (32 row bands)
__device__ float2 g_part[32][4][128];
__device__ int    g_cnt[32];    // LN partial barrier
__device__ int    g_cnt1[32];   // phase1 (h1) done per band
__device__ int    g_cnt2[32];   // phase2 (h2) done per band

// ---------------------------------------------------------------------------
// helpers
// ---------------------------------------------------------------------------
__device__ __forceinline__ uint32_t smem_u32(const void* p) {
    uint32_t a;
    asm("{ .reg .u64 t; cvta.to.shared.u64 t, %1; cvt.u32.u64 %0, t; }"
        : "=r"(a) : "l"(p));
    return a;
}
__device__ __forceinline__ uint32_t sw128(uint32_t off) {
    return off ^ ((off >> 3) & 0x70);
}
__device__ __forceinline__ void split_bf16(float v, __nv_bfloat16& hi, __nv_bfloat16& lo) {
    hi = __float2bfloat16(v);
    lo = __float2bfloat16(v - __bfloat162float(hi));
}

#define CP_ASYNC16(smem_a, gptr)                                               \
    asm volatile("cp.async.cg.shared.global [%0], [%1], 16;"                   \
                 :: "r"((uint32_t)(smem_a)), "l"(gptr) : "memory")
#define CP_MBAR_ARRIVE(mbar)                                                   \
    asm volatile("cp.async.mbarrier.arrive.noinc.shared.b64 [%0];"             \
                 :: "r"((uint32_t)(mbar)) : "memory")
#define MBARRIER_INIT(mbar, cnt)                                               \
    asm volatile("mbarrier.init.shared.b64 [%0], %1;"                          \
                 :: "r"((uint32_t)(mbar)), "r"((uint32_t)(cnt)) : "memory")
#define MBARRIER_WAIT_PARITY(mbar_a, par_a) do {                               \
    uint32_t _mb = (uint32_t)(mbar_a);                                         \
    uint32_t _pa = (uint32_t)(par_a);                                          \
    uint32_t _done;                                                            \
    asm volatile("{\n\t.reg .pred p;\n\t"                                      \
        "mbarrier.try_wait.parity.acquire.cta.shared::cta.b64 p, [%1], %2;\n\t"\
        "selp.b32 %0, 1, 0, p;\n\t}"                                           \
        : "=r"(_done) : "r"(_mb), "r"(_pa) : "memory");                        \
    if (!_done) {                                                              \
        asm volatile("{\n\t.reg .pred P1;\n\t"                                 \
            "WL_%=:\n\t"                                                       \
            "mbarrier.try_wait.parity.acquire.cta.shared::cta.b64 P1, [%0], %1, 0x989680;\n\t" \
            "@P1 bra.uni WD_%=;\n\t"                                           \
            "bra.uni WL_%=;\n\t"                                               \
            "WD_%=:\n\t}" :: "r"(_mb), "r"(_pa) : "memory");                   \
    }                                                                          \
} while (0)

#if HAS_TCGEN05
__device__ __forceinline__ uint32_t elect_one() {
    uint32_t pred;
    asm volatile("{\n\t.reg .pred p;\n\telect.sync _|p, 0xFFFFFFFF;\n\t"
                 "selp.b32 %0, 1, 0, p;\n\t}" : "=r"(pred));
    return pred;
}
#define TCGEN05_ALLOC(sm_addr, ncols)                                          \
    asm volatile("tcgen05.alloc.cta_group::1.sync.aligned.shared::cta.b32 [%0], %1;" \
                 :: "r"((uint32_t)(sm_addr)), "r"((uint32_t)(ncols)) : "memory")
#define TCGEN05_DEALLOC(tmem, ncols)                                           \
    asm volatile("tcgen05.dealloc.cta_group::1.sync.aligned.b32 %0, %1;"       \
                 :: "r"(tmem), "r"((uint32_t)(ncols)))
#define TCGEN05_RELINQ()                                                       \
    asm volatile("tcgen05.relinquish_alloc_permit.cta_group::1.sync.aligned;")
#define TCGEN05_COMMIT(mbar)                                                   \
    asm volatile("tcgen05.commit.cta_group::1.mbarrier::arrive::one.shared::cluster.b64 [%0];" \
                 :: "r"((uint32_t)(mbar)) : "memory")
#define TCGEN05_WAIT_LD() asm volatile("tcgen05.wait::ld.sync.aligned;" ::: "memory")
#define TCGEN05_FENCE_AFTER() asm volatile("tcgen05.fence::after_thread_sync;" ::: "memory")
#define FENCE_ASYNC_SHARED() asm volatile("fence.proxy.async.shared::cta;" ::: "memory")

#define TCGEN05_LD_X32(r, tmem_addr)                                           \
    asm volatile("tcgen05.ld.sync.aligned.32x32b.x32.b32 "                     \
        "{%0, %1, %2, %3, %4, %5, %6, %7, "                                    \
        " %8, %9, %10, %11, %12, %13, %14, %15, "                              \
        " %16, %17, %18, %19, %20, %21, %22, %23, "                            \
        " %24, %25, %26, %27, %28, %29, %30, %31}, [%32];"                     \
        : "=r"((r)[0]),  "=r"((r)[1]),  "=r"((r)[2]),  "=r"((r)[3]),           \
          "=r"((r)[4]),  "=r"((r)[5]),  "=r"((r)[6]),  "=r"((r)[7]),           \
          "=r"((r)[8]),  "=r"((r)[9]),  "=r"((r)[10]), "=r"((r)[11]),          \
          "=r"((r)[12]), "=r"((r)[13]), "=r"((r)[14]), "=r"((r)[15]),          \
          "=r"((r)[16]), "=r"((r)[17]), "=r"((r)[18]), "=r"((r)[19]),          \
          "=r"((r)[20]), "=r"((r)[21]), "=r"((r)[22]), "=r"((r)[23]),          \
          "=r"((r)[24]), "=r"((r)[25]), "=r"((r)[26]), "=r"((r)[27]),          \
          "=r"((r)[28]), "=r"((r)[29]), "=r"((r)[30]), "=r"((r)[31])           \
        : "r"(tmem_addr))

__device__ __forceinline__ void mma_bf16_ss(uint32_t d, uint64_t a, uint64_t b,
                                            uint32_t idesc, uint32_t en) {
    asm volatile(
        "{\n\t.reg .pred p;\n\tsetp.ne.u32 p, %4, 0;\n\t"
        "tcgen05.mma.cta_group::1.kind::f16 [%0], %1, %2, %3, {%5, %5, %5, %5}, p;\n\t}"
        :: "r"(d), "l"(a), "l"(b), "r"(idesc), "r"(en), "r"(0u) : "memory");
}
__device__ __forceinline__ uint64_t make_desc(uint32_t addr) {
    return ((uint64_t)2 << 61) | ((uint64_t)1 << 46) | ((uint64_t)64 << 32) |
           ((uint64_t)1 << 16) | ((uint64_t)(addr >> 4) & 0x3FFF);
}
static constexpr uint32_t IDESC_128x128 = 0x8200490u;
#endif  // HAS_TCGEN05

// ---------------------------------------------------------------------------
// Prep: object mean + weight transpose/split + barrier counter reset
// ---------------------------------------------------------------------------
__global__ void prep_kernel(const float* __restrict__ states,
                            const float* __restrict__ W1,
                            const float* __restrict__ W2,
                            const float* __restrict__ W3) {
    if (blockIdx.x == 0 && threadIdx.x < 32) {
        g_cnt[threadIdx.x]  = 0;
        g_cnt1[threadIdx.x] = 0;
        g_cnt2[threadIdx.x] = 0;
    }
    if (blockIdx.x < 1024) {
        int lb = threadIdx.x >> 6;
        int d4 = threadIdx.x & 63;
        int b  = blockIdx.x * 4 + lb;
        const float4* src = (const float4*)(states + (size_t)b * OBJ * OBS);
        float4 acc = make_float4(0.f, 0.f, 0.f, 0.f);
#pragma unroll
        for (int o = 0; o < OBJ; ++o) {
            float4 v = src[o * (OBS / 4) + d4];
            acc.x += v.x; acc.y += v.y; acc.z += v.z; acc.w += v.w;
        }
        const float inv = 1.0f / OBJ;
        float vals[4] = {acc.x * inv, acc.y * inv, acc.z * inv, acc.w * inv};
        size_t base = (size_t)b * OBS + d4 * 4;
#pragma unroll
        for (int c = 0; c < 4; ++c) {
            __nv_bfloat16 hi, lo; split_bf16(vals[c], hi, lo);
            g_sbar_h[base + c] = hi; g_sbar_l[base + c] = lo;
        }
    } else {
        int r = blockIdx.x - 1024;
        int bz = r >> 8;
        int rem = r & 255;
        int bx = rem & 15, by = rem >> 4;
        const float* W; __nv_bfloat16 *Th, *Tl; int K, N;
        if (bz == 0)      { W = W1; Th = g_W1T_h; Tl = g_W1T_l; K = OBS; N = HID; }
        else if (bz == 1) { W = W2; Th = g_W2T_h; Tl = g_W2T_l; K = HID; N = HID; }
        else              { W = W3; Th = g_W3T_h; Tl = g_W3T_l; K = HID; N = OBS; }
        int k0 = by * 32, n0 = bx * 32;
        if (k0 >= K || n0 >= N) return;
        __shared__ float t[32][33];
        int tx = threadIdx.x & 31, ty = threadIdx.x >> 5;
#pragma unroll
        for (int i = 0; i < 4; ++i)
            t[ty + i * 8][tx] = W[(size_t)(k0 + ty + i * 8) * N + n0 + tx];
        __syncthreads();
#pragma unroll
        for (int i = 0; i < 4; ++i) {
            int n = ty + i * 8;
            float v = t[tx][n];
            __nv_bfloat16 hi, lo; split_bf16(v, hi, lo);
            size_t o = (size_t)(n0 + n) * K + k0 + tx;
            Th[o] = hi; Tl[o] = lo;
        }
    }
}

// ---------------------------------------------------------------------------
// smem layout (megakernel). Non-overlapping regions:
//   [0,8)      tmem ptr
//   [16,160)   18 mbarriers (3 phases x (3 FULL + 3 EMPTY))
//   [192,704)  s_bias (128 f32)
//   [704,2752) s_aux: phase1 = 512 f32 W1 rows; phase2 = 128 f32 ln_g (first 512B)
//   [1216,1728) s_b2 (phase2 only; s_aux phase2 uses [704,1216) only)
//   [1728,2240) s_mu (phase2 only)
//   [2752,3264) s_rs (phase2 only)
//   [3264,3776) s_jrow (phase1 only; CLEAR of s_aux [704,2752))  <- R9 bug fix
//   [4096, ...) tiles / s_d staging
// ---------------------------------------------------------------------------
static constexpr int SM_TMEMPTR = 0;
static constexpr int SM_MBAR    = 16;
static constexpr int SM_BIAS    = 192;
static constexpr int SM_AUX     = 704;
static constexpr int SM_LNB2    = 1216;
static constexpr int SM_MU2     = 1728;
static constexpr int SM_RS2     = 2752;
static constexpr int SM_JROW    = 3264;   // fixed: was 2240, inside s_aux
static constexpr int SM_TILES   = 4096;
static constexpr int TILE_BYTES = 128 * 128;
static constexpr int NSLOT      = 3;
static constexpr int STG_STRIDE = 132;
static constexpr int GEMM_SMEM  = SM_TILES + NSLOT * 4 * TILE_BYTES;  // 200704

// ---------------------------------------------------------------------------
// Pipelined bf16-split GEMM mainloop; stages D(+s_bias) into s_d.
// ---------------------------------------------------------------------------
#if HAS_TCGEN05
__device__ __forceinline__ void gemm_pipeline(
    char* sm, uint32_t smb, int tid, int wid, int lid, uint32_t tmem,
    const __nv_bfloat16* Ah, const __nv_bfloat16* Al,
    const __nv_bfloat16* BTh, const __nv_bfloat16* BTl,
    int m0, int n0, int Ktot, uint32_t mbofs) {
    const uint32_t mb_full  = smb + mbofs;
    const uint32_t mb_empty = smb + mbofs + 24;
    const __nv_bfloat16* srcs[4] = {Ah, Al, BTh, BTl};
    const int row0s[4] = {m0, m0, n0, n0};
    const int NC = Ktot >> 6;

    auto load_stage = [&](int chunk, int slot) {
        const int kt = chunk << 6;
#pragma unroll
        for (int t = 0; t < 4; ++t) {
            uint32_t st = smb + SM_TILES + (uint32_t)(slot * 4 + t) * TILE_BYTES;
            const __nv_bfloat16* g = srcs[t];
            const int r0 = row0s[t];
#pragma unroll
            for (int ii = 0; ii < 4; ++ii) {
                int idx = tid + ii * 256;
                int r = idx >> 3, q = idx & 7;
                CP_ASYNC16(st + sw128(r * 128 + q * 16),
                           g + (size_t)(r0 + r) * Ktot + kt + q * 8);
            }
        }
        CP_MBAR_ARRIVE(mb_full + slot * 8);
    };

#pragma unroll
    for (int c = 0; c < NSLOT; ++c) load_stage(c, c);

    const bool consumer = (wid == 0) && elect_one();
    for (int c = 0; c < NC; ++c) {
        const int s = c % NSLOT;
        const int k = c / NSLOT;
        if (consumer) {
            MBARRIER_WAIT_PARITY(mb_full + s * 8, k & 1);
            FENCE_ASYNC_SHARED();
            uint32_t base = smb + SM_TILES + (uint32_t)(s * 4) * TILE_BYTES;
            uint64_t dAh = make_desc(base);
            uint64_t dAl = make_desc(base + TILE_BYTES);
            uint64_t dBh = make_desc(base + 2 * TILE_BYTES);
            uint64_t dBl = make_desc(base + 3 * TILE_BYTES);
#pragma unroll
            for (int ks = 0; ks < 4; ++ks) {
                mma_bf16_ss(tmem, dAh + ks * 2, dBh + ks * 2, IDESC_128x128,
                            (c > 0 || ks > 0) ? 1u : 0u);
                mma_bf16_ss(tmem, dAh + ks * 2, dBl + ks * 2, IDESC_128x128, 1u);
                mma_bf16_ss(tmem, dAl + ks * 2, dBh + ks * 2, IDESC_128x128, 1u);
            }
            TCGEN05_COMMIT(mb_empty + s * 8);
        }
        if (c + NSLOT < NC) {
            MBARRIER_WAIT_PARITY(mb_empty + s * 8, k & 1);
            load_stage(c + NSLOT, s);
        }
    }
    {
        const int cl = NC - 1;
        MBARRIER_WAIT_PARITY(mb_empty + (cl % NSLOT) * 8, (cl / NSLOT) & 1);
    }
    TCGEN05_FENCE_AFTER();

    float* s_d = (float*)(sm + SM_TILES);
    const float* s_bias = (const float*)(sm + SM_BIAS);
    {
        const int wq = wid & 3, wc = wid >> 2;
        const int row = wq * 32 + lid;
#pragma unroll
        for (int cc = 0; cc < 2; ++cc) {
            const int cb = wc * 64 + cc * 32;
            uint32_t d[32];
            TCGEN05_LD_X32(d, tmem + cb);
            TCGEN05_WAIT_LD();
#pragma unroll
            for (int c = 0; c < 32; ++c)
                s_d[row * STG_STRIDE + cb + c] = __uint_as_float(d[c]) + s_bias[cb + c];
        }
    }
    __syncthreads();
}
#else
__device__ __forceinline__ void gemm_pipeline(
    char* sm, uint32_t smb, int tid, int wid, int lid, uint32_t tmem,
    const __nv_bfloat16* Ah, const __nv_bfloat16* Al,
    const __nv_bfloat16* BTh, const __nv_bfloat16* BTl,
    int m0, int n0, int Ktot, uint32_t mbofs) {
    float* s_d = (float*)(sm + SM_TILES);
    const float* s_bias = (const float*)(sm + SM_BIAS);
    __syncthreads();
    for (int e = tid; e < 128 * 128; e += 256) {
        int r = e >> 7, c = e & 127;
        float acc = 0.f;
        for (int k = 0; k < Ktot; ++k) {
            float a = __bfloat162float(Ah[(size_t)(m0 + r) * Ktot + k]) +
                      __bfloat162float(Al[(size_t)(m0 + r) * Ktot + k]);
            float b = __bfloat162float(BTh[(size_t)(n0 + c) * Ktot + k]) +
                      __bfloat162float(BTl[(size_t)(n0 + c) * Ktot + k]);
            acc += a * b;
        }
        s_d[r * STG_STRIDE + c] = acc + s_bias[c];
    }
    __syncthreads();
}
#endif

// band spin barrier: arrive (tid==0) then wait until cnt reaches target
__device__ __forceinline__ void band_arrive_wait(int* cnt, int target, int tid) {
    __syncthreads();
    if (tid == 0) {
        __threadfence();
        atomicAdd(cnt, 1);
        while (atomicAdd(cnt, 0) < target) {}
        __threadfence();
    }
    __syncthreads();
}

// ---------------------------------------------------------------------------
// Megakernel: phase1 (h1) -> phase2 (h2 = relu(LN(...))) -> phase3 (out).
// grid (4, 32); 128 CTAs x 200KB smem = 1 CTA/SM, all co-resident.
// ---------------------------------------------------------------------------
__global__ __launch_bounds__(256, 1)
void mega_kernel(const int* __restrict__ action,
                 const float* __restrict__ W1,
                 const float* __restrict__ b1,
                 const float* __restrict__ b2,
                 const float* __restrict__ b3,
                 const float* __restrict__ ln_g,
                 const float* __restrict__ ln_b,
                 float* __restrict__ out) {
    extern __shared__ char sm[];
    const uint32_t smb = smem_u32(sm);
    const int tid = threadIdx.x;
    const int wid = tid >> 5;
    const int lid = tid & 31;
    const int x  = blockIdx.x;     // 0..3
    const int by = blockIdx.y;     // band 0..31
    const int m0 = by * 128;

    float* s_bias = (float*)(sm + SM_BIAS);
    float* s_aux  = (float*)(sm + SM_AUX);    // phase1: W1 rows; phase2: ln_g
    int*   s_jrow = (int*)(sm + SM_JROW);
    float* s_b2   = (float*)(sm + SM_LNB2);
    float* s_mu   = (float*)(sm + SM_MU2);
    float* s_rs   = (float*)(sm + SM_RS2);
    float* s_d    = (float*)(sm + SM_TILES);

    uint32_t tmem = 0;
#if HAS_TCGEN05
    if (wid == 0) TCGEN05_ALLOC(smb + SM_TMEMPTR, 128);
    if (tid == 0) {
#pragma unroll
        for (int p = 0; p < 3; ++p) {
#pragma unroll
            for (int s = 0; s < NSLOT; ++s) {
                MBARRIER_INIT(smb + SM_MBAR + p * 48 + s * 8, 256);
                MBARRIER_INIT(smb + SM_MBAR + p * 48 + 24 + s * 8, 1);
            }
        }
    }
#endif
    // ---------------- phase 1: h1 ----------------
    {
        const int n0 = x * 128;
        if (tid < 128) {
            s_bias[tid] = b1[n0 + tid];
            s_jrow[tid] = (action[m0 + tid] & 3) * 128;
        }
        for (int idx = tid; idx < 512; idx += 256)
            s_aux[idx] = W1[(size_t)(256 + (idx >> 7)) * HID + n0 + (idx & 127)];
        __syncthreads();
#if HAS_TCGEN05
        asm volatile("ld.shared.b32 %0, [%1];" : "=r"(tmem) : "r"(smb + SM_TMEMPTR));
#endif
        gemm_pipeline(sm, smb, tid, wid, lid, tmem,
                      g_sbar_h, g_sbar_l, g_W1T_h, g_W1T_l, m0, n0, OBS,
                      SM_MBAR + 0 * 48);
#pragma unroll
        for (int it = 0; it < 16; ++it) {
            int idx = it * 256 + tid;
            int row = idx >> 5, c4 = (idx & 31) * 4;
            int jr = s_jrow[row];
            float4 v = *(float4*)&s_d[row * STG_STRIDE + c4];
            float f0 = fmaxf(v.x + 0.0625f * s_aux[jr + c4 + 0], 0.f);
            float f1 = fmaxf(v.y + 0.0625f * s_aux[jr + c4 + 1], 0.f);
            float f2 = fmaxf(v.z + 0.0625f * s_aux[jr + c4 + 2], 0.f);
            float f3 = fmaxf(v.w + 0.0625f * s_aux[jr + c4 + 3], 0.f);
            __nv_bfloat16 h0, l0, h1, l1, h2, l2, h3, l3;
            split_bf16(f0, h0, l0); split_bf16(f1, h1, l1);
            split_bf16(f2, h2, l2); split_bf16(f3, h3, l3);
            __nv_bfloat162 hp0(h0, h1), hp1(h2, h3), lp0(l0, l1), lp1(l2, l3);
            uint2 hv = make_uint2(*(uint32_t*)&hp0, *(uint32_t*)&hp1);
            uint2 lv = make_uint2(*(uint32_t*)&lp0, *(uint32_t*)&lp1);
            size_t o = (size_t)(m0 + row) * HID + n0 + c4;
            *(uint2*)(g_h1_h + o) = hv;
            *(uint2*)(g_h1_l + o) = lv;
        }
        band_arrive_wait(&g_cnt1[by], 4, tid);
    }

    // ---------------- phase 2: h2 = relu(LN(h1 @ W2 + b2)) ----------------
    {
        const int n0 = x * 128;
        if (tid < 128) {
            s_bias[tid] = b2[n0 + tid];
            s_aux[tid]  = ln_g[n0 + tid];
            s_b2[tid]   = ln_b[n0 + tid];
        }
        __syncthreads();
        gemm_pipeline(sm, smb, tid, wid, lid, tmem,
                      g_h1_h, g_h1_l, g_W2T_h, g_W2T_l, m0, n0, HID,
                      SM_MBAR + 1 * 48);
        // per-row partials over this CTA's 128 cols (2 threads/row)
        {
            int prow = tid >> 1, ph = tid & 1;
            float s = 0.f, ss = 0.f;
#pragma unroll
            for (int i = 0; i < 16; ++i) {
                float4 v = *(float4*)&s_d[prow * STG_STRIDE + ph * 64 + i * 4];
                s  += v.x + v.y + v.z + v.w;
                ss += v.x * v.x + v.y * v.y + v.z * v.z + v.w * v.w;
            }
            s  += __shfl_xor_sync(0xffffffffu, s, 1);
            ss += __shfl_xor_sync(0xffffffffu, ss, 1);
            if (ph == 0) g_part[by][x][prow] = make_float2(s, ss);
        }
        band_arrive_wait(&g_cnt[by], 4, tid);
        if (tid < 128) {
            float ts = 0.f, tss = 0.f;
#pragma unroll
            for (int r = 0; r < 4; ++r) {
                float2 p = __ldcg(&g_part[by][r][tid]);
                ts += p.x; tss += p.y;
            }
            const float invn = 1.0f / HID;
            float mu = ts * invn;
            float var = tss * invn - mu * mu;
            s_mu[tid] = mu;
            s_rs[tid] = rsqrtf(var + 1e-5f);
        }
        __syncthreads();
#pragma unroll
        for (int it = 0; it < 16; ++it) {
            int idx = it * 256 + tid;
            int row = idx >> 5, c4 = (idx & 31) * 4;
            float mu = s_mu[row], rs = s_rs[row];
            float4 v = *(float4*)&s_d[row * STG_STRIDE + c4];
            float f0 = fmaxf((v.x - mu) * rs * s_aux[c4 + 0] + s_b2[c4 + 0], 0.f);
            float f1 = fmaxf((v.y - mu) * rs * s_aux[c4 + 1] + s_b2[c4 + 1], 0.f);
            float f2 = fmaxf((v.z - mu) * rs * s_aux[c4 + 2] + s_b2[c4 + 2], 0.f);
            float f3 = fmaxf((v.w - mu) * rs * s_aux[c4 + 3] + s_b2[c4 + 3], 0.f);
            __nv_bfloat16 h0, l0, h1, l1, h2, l2, h3, l3;
            split_bf16(f0, h0, l0); split_bf16(f1, h1, l1);
            split_bf16(f2, h2, l2); split_bf16(f3, h3, l3);
            __nv_bfloat162 hp0(h0, h1), hp1(h2, h3), lp0(l0, l1), lp1(l2, l3);
            uint2 hv = make_uint2(*(uint32_t*)&hp0, *(uint32_t*)&hp1);
            uint2 lv = make_uint2(*(uint32_t*)&lp0, *(uint32_t*)&lp1);
            size_t o = (size_t)(m0 + row) * HID + n0 + c4;
            *(uint2*)(g_h2_h + o) = hv;
            *(uint2*)(g_h2_l + o) = lv;
        }
        band_arrive_wait(&g_cnt2[by], 4, tid);
    }

    // ---------------- phase 3: out = broadcast_obj(h2 @ W3 + b3) ----------
    {
        const int n0 = (x & 1) * 128;
        const int z  = x >> 1;          // object half: 0 -> obj 0..7, 1 -> 8..15
        if (tid < 128) s_bias[tid] = b3[n0 + tid];
        __syncthreads();
        gemm_pipeline(sm, smb, tid, wid, lid, tmem,
                      g_h2_h, g_h2_l, g_W3T_h, g_W3T_l, m0, n0, HID,
                      SM_MBAR + 2 * 48);
#pragma unroll
        for (int it = 0; it < 16; ++it) {
            int idx = it * 256 + tid;
            int row = idx >> 5, c4 = (idx & 31) * 4;
            float4 v = *(float4*)&s_d[row * STG_STRIDE + c4];
            size_t base = (size_t)(m0 + row) * (OBJ * OBS) +
                          (size_t)(z * 8) * OBS + n0 + c4;
#pragma unroll
            for (int ob = 0; ob < 8; ++ob)
                *(float4*)(out + base + (size_t)ob * OBS) = v;
        }
    }

#if HAS_TCGEN05
    __syncthreads();
    if (wid == 0) {
        TCGEN05_RELINQ();
        TCGEN05_DEALLOC(tmem, 128);
    }
#endif
}

// ---------------------------------------------------------------------------
extern "C" void kernel_launch(void* const* d_in, const int* in_sizes, int n_in,
                              void* d_out, int out_size) {
    const float* states = (const float*)d_in[0];
    const int*   action = (const int*)d_in[1];
    const float* W1     = (const float*)d_in[2];
    const float* b1     = (const float*)d_in[3];
    const float* W2     = (const float*)d_in[4];
    const float* b2     = (const float*)d_in[5];
    const float* W3     = (const float*)d_in[6];
    const float* b3     = (const float*)d_in[7];
    const float* ln_g   = (const float*)d_in[8];
    const float* ln_b   = (const float*)d_in[9];
    float* out = (float*)d_out;

    cudaFuncSetAttribute(mega_kernel,
                         cudaFuncAttributeMaxDynamicSharedMemorySize, GEMM_SMEM);

    // 0) prep: object mean + weight transpose/split + barrier reset
    prep_kernel<<<1792, 256>>>(states, W1, W2, W3);
    // 1) fused GEMM1 -> GEMM2+LN -> GEMM3 with per-band spin barriers
    mega_kernel<<<dim3(4, 32), 256, GEMM_SMEM>>>(
        action, W1, b1, b2, b3, ln_g, ln_b, out);
}